// round 13
// baseline (speedup 1.0000x reference)
#include <cuda_runtime.h>
#include <cuda_fp16.h>
#include <cstdint>

#define NROWS 131072
#define BB 32
#define OO 4096
#define FF 256
#define HH 8
#define HID 128
#define NBLK_A 1024   // NROWS / 128

// ---------------- scratch (device globals) ----------------
__device__ __half d_h[NROWS * HID];
__device__ __half d_z[NROWS * HID];
__device__ float d_mask[NROWS];
__device__ float d_colpart[NBLK_A * 256];
__device__ float d_ss[256];
__device__ float d_t[NROWS * HH];
__device__ float d_cmax[BB * 8 * HH];
__device__ float d_csum[BB * 8 * HH];
__device__ float d_M[BB * HH];
__device__ float d_invS[BB * HH];
__device__ float d_partial[BB * 16 * HH * FF];
__device__ __half d_WinT[HID * FF];
__device__ __half d_WblkT[HID * HID];

// ---------------- smem layout for kA (bytes) ----------------
// staging: 2 x (128 rows x 128 cols fp32) for cp.async x chunks
// A tile : 128 x 128 fp16, row stride 272 B;  B tile same
#define STG0  0                    // 65536
#define STG1  65536                // 65536
#define AS    131072               // 34816
#define BS    165888               // 34816
#define ROWSQ 200704               // 128 floats
#define WSUM  201216               // 8*128 floats
#define WSQ   205312               // 8*128 floats
#define SMEM_TOTAL 209408          // 1 CTA/SM

// ---------------- smem layout for kC (bytes) ----------------
#define KC_WF  34816               // 8 x 136 fp16
#define KC_SC  36992
#define KC_SH  37504
#define KC_BFC 38016
#define KC_SMEM 38048

// ---------------- helpers ----------------
__device__ __forceinline__ uint32_t smem_u32(const void* p) {
    uint32_t a;
    asm("{ .reg .u64 t; cvta.to.shared.u64 t, %1; cvt.u32.u64 %0, t; }" : "=r"(a) : "l"(p));
    return a;
}
__device__ __forceinline__ void ldsm4(uint32_t* r, uint32_t addr) {
    asm volatile("ldmatrix.sync.aligned.m8n8.x4.shared.b16 {%0,%1,%2,%3}, [%4];"
        : "=r"(r[0]), "=r"(r[1]), "=r"(r[2]), "=r"(r[3]) : "r"(addr));
}
__device__ __forceinline__ void ldsm2(uint32_t& r0, uint32_t& r1, uint32_t addr) {
    asm volatile("ldmatrix.sync.aligned.m8n8.x2.shared.b16 {%0,%1}, [%2];"
        : "=r"(r0), "=r"(r1) : "r"(addr));
}
__device__ __forceinline__ void mma16816(float* c, const uint32_t* a, uint32_t b0, uint32_t b1) {
    asm volatile("mma.sync.aligned.m16n8k16.row.col.f32.f16.f16.f32 "
        "{%0,%1,%2,%3}, {%4,%5,%6,%7}, {%8,%9}, {%0,%1,%2,%3};"
        : "+f"(c[0]), "+f"(c[1]), "+f"(c[2]), "+f"(c[3])
        : "r"(a[0]), "r"(a[1]), "r"(a[2]), "r"(a[3]), "r"(b0), "r"(b1));
}
__device__ __forceinline__ uint32_t packh(float a, float b) {
    __half2 hp = __floats2half2_rn(a, b);
    return *reinterpret_cast<uint32_t*>(&hp);
}
#define CP_ASYNC16(dst, src) \
    asm volatile("cp.async.cg.shared.global [%0], [%1], 16;" :: "r"(dst), "l"(src) : "memory")
#define CP_COMMIT() asm volatile("cp.async.commit_group;" ::: "memory")
#define CP_WAIT(n)  asm volatile("cp.async.wait_group %0;" :: "n"(n) : "memory")

// ============================================================================
// kW: convert weights to fp16, transposed to [N][K]
// ============================================================================
__global__ void kW(const float* __restrict__ Win, const float* __restrict__ Wblk) {
    int e = blockIdx.x * 256 + threadIdx.x;
    if (e < HID * FF) {
        int n = e >> 8, k = e & 255;
        d_WinT[e] = __float2half_rn(Win[(size_t)k * HID + n]);
    }
    if (e < HID * HID) {
        int n = e >> 7, k = e & 127;
        d_WblkT[e] = __float2half_rn(Wblk[(size_t)k * HID + n]);
    }
}

// ============================================================================
// kA_mma: h = relu(x@Win+b); z = h@Wblk+b; BN col partials; row mask
// cp.async double-buffered x staging: both chunks issued at entry; chunk1's
// DRAM transfer overlaps chunk0's convert+MMA.
// ============================================================================
__global__ __launch_bounds__(512, 1) void kA_mma(
    const float* __restrict__ x, const float* __restrict__ bin,
    const float* __restrict__ bblk)
{
    extern __shared__ char smem[];
    const uint32_t sb = smem_u32(smem);
    const int tid = threadIdx.x;
    const int lane = tid & 31;
    const int w = tid >> 5;
    const int wr = w >> 1;        // row group 0..7 (16 rows each)
    const int wc = w & 1;         // col half 0..1 (64 cols each)
    const int row0 = blockIdx.x * 128;

    float* rowsq = (float*)(smem + ROWSQ);
    float* wS = (float*)(smem + WSUM);
    float* wQ = (float*)(smem + WSQ);
    if (tid < 128) rowsq[tid] = 0.f;

    // issue cp.async for BOTH x chunks up front (fp32 -> staging)
#pragma unroll
    for (int i = 0; i < 8; i++) {
        int idx = tid + i * 512;
        int r = idx >> 5, c4 = idx & 31;
        CP_ASYNC16(sb + STG0 + (uint32_t)(r * 512 + c4 * 16),
                   x + (size_t)(row0 + r) * FF + c4 * 4);
    }
    CP_COMMIT();
#pragma unroll
    for (int i = 0; i < 8; i++) {
        int idx = tid + i * 512;
        int r = idx >> 5, c4 = idx & 31;
        CP_ASYNC16(sb + STG1 + (uint32_t)(r * 512 + c4 * 16),
                   x + (size_t)(row0 + r) * FF + 128 + c4 * 4);
    }
    CP_COMMIT();

    float acc[8][4];
#pragma unroll
    for (int nt = 0; nt < 8; nt++)
#pragma unroll
        for (int j = 0; j < 4; j++) acc[nt][j] = 0.f;

    // ldmatrix lane bases
    const uint32_t aBase = sb + AS +
        (uint32_t)((wr * 16 + (lane & 15)) * 272 + ((lane >> 4) << 3) * 2);
    const uint32_t bBase = sb + BS + (uint32_t)(wc * 64 * 272 +
        ((lane & 7) + ((lane >> 4) << 3)) * 272 + ((lane >> 3) & 1) * 16);

    // B0: WinT cols [0,128) (L2-hot after first wave)
#pragma unroll
    for (int i = 0; i < 4; i++) {
        int idx = tid + i * 512;
        int n = idx >> 4, q = idx & 15;
        *(uint4*)(smem + BS + (uint32_t)(n * 272 + q * 16)) =
            *(const uint4*)(d_WinT + (size_t)n * FF + q * 8);
    }
    __syncthreads();   // rowsq init visible; B0 in smem

    // ---- chunk 0: convert staging0 -> A (each thread reads its own bytes) ----
    CP_WAIT(1);
#pragma unroll
    for (int i = 0; i < 8; i++) {
        int idx = tid + i * 512;
        int r = idx >> 5, c4 = idx & 31;
        float4 v = *(const float4*)(smem + STG0 + (uint32_t)(r * 512 + c4 * 16));
        int nz = (v.x != 0.f) | (v.y != 0.f) | (v.z != 0.f) | (v.w != 0.f);
        if (__any_sync(0xffffffffu, nz) && lane == 0) rowsq[r] = 1.f;
        *(uint2*)(smem + AS + (uint32_t)(r * 272 + c4 * 8)) =
            make_uint2(packh(v.x, v.y), packh(v.z, v.w));
    }
    __syncthreads();

    // ---- MMA chunk 0 (x1 cp.async still in flight underneath) ----
#pragma unroll
    for (int ks = 0; ks < 8; ks++) {
        uint32_t ah[4];
        ldsm4(ah, aBase + ks * 32);
#pragma unroll
        for (int p = 0; p < 4; p++) {
            uint32_t bh[4];
            ldsm4(bh, bBase + p * 4352 + ks * 32);
            mma16816(acc[2 * p],     ah, bh[0], bh[1]);
            mma16816(acc[2 * p + 1], ah, bh[2], bh[3]);
        }
    }
    __syncthreads();   // drain chunk-0 reads of A and B tiles

    // B1: WinT cols [128,256)
#pragma unroll
    for (int i = 0; i < 4; i++) {
        int idx = tid + i * 512;
        int n = idx >> 4, q = idx & 15;
        *(uint4*)(smem + BS + (uint32_t)(n * 272 + q * 16)) =
            *(const uint4*)(d_WinT + (size_t)n * FF + 128 + q * 8);
    }
    // ---- chunk 1: convert staging1 -> A ----
    CP_WAIT(0);
#pragma unroll
    for (int i = 0; i < 8; i++) {
        int idx = tid + i * 512;
        int r = idx >> 5, c4 = idx & 31;
        float4 v = *(const float4*)(smem + STG1 + (uint32_t)(r * 512 + c4 * 16));
        int nz = (v.x != 0.f) | (v.y != 0.f) | (v.z != 0.f) | (v.w != 0.f);
        if (__any_sync(0xffffffffu, nz) && lane == 0) rowsq[r] = 1.f;
        *(uint2*)(smem + AS + (uint32_t)(r * 272 + c4 * 8)) =
            make_uint2(packh(v.x, v.y), packh(v.z, v.w));
    }
    __syncthreads();

    // ---- MMA chunk 1 ----
#pragma unroll
    for (int ks = 0; ks < 8; ks++) {
        uint32_t ah[4];
        ldsm4(ah, aBase + ks * 32);
#pragma unroll
        for (int p = 0; p < 4; p++) {
            uint32_t bh[4];
            ldsm4(bh, bBase + p * 4352 + ks * 32);
            mma16816(acc[2 * p],     ah, bh[0], bh[1]);
            mma16816(acc[2 * p + 1], ah, bh[2], bh[3]);
        }
    }
    // RACE FIX: both col-half warps read all k of the shared A rows above;
    // epilogue 1 overwrites those rows with h. Drain block-wide first.
    __syncthreads();

    // ---------------- epilogue 1: h = relu(acc + bin) ----------------
    const int qrow = lane >> 2, qcol = lane & 3;
    const int r0 = wr * 16 + qrow;
#pragma unroll
    for (int nt = 0; nt < 8; nt++) {
        int c0 = wc * 64 + nt * 8 + qcol * 2;
        float b0v = bin[c0], b1v = bin[c0 + 1];
        float h00 = fmaxf(acc[nt][0] + b0v, 0.f);
        float h01 = fmaxf(acc[nt][1] + b1v, 0.f);
        float h10 = fmaxf(acc[nt][2] + b0v, 0.f);
        float h11 = fmaxf(acc[nt][3] + b1v, 0.f);
        uint32_t p00 = packh(h00, h01);
        uint32_t p10 = packh(h10, h11);
        *(uint32_t*)(d_h + (size_t)(row0 + r0) * HID + c0)     = p00;
        *(uint32_t*)(d_h + (size_t)(row0 + r0 + 8) * HID + c0) = p10;
        *(uint32_t*)(smem + AS + (r0 * 136 + c0) * 2)       = p00;
        *(uint32_t*)(smem + AS + ((r0 + 8) * 136 + c0) * 2) = p10;
        acc[nt][0] = acc[nt][1] = acc[nt][2] = acc[nt][3] = 0.f;
    }
    __syncthreads();

    // B: WblkT [128n][128k] fp16
#pragma unroll
    for (int i = 0; i < 4; i++) {
        int idx = tid + i * 512;
        int n = idx >> 4, q = idx & 15;
        *(uint4*)(smem + BS + (uint32_t)(n * 272 + q * 16)) =
            *(const uint4*)(d_WblkT + (size_t)n * HID + q * 8);
    }
    __syncthreads();

    // ---------------- GEMM2: z = h @ Wblk, K=128 ----------------
#pragma unroll
    for (int ks = 0; ks < 8; ks++) {
        uint32_t ah[4];
        ldsm4(ah, aBase + ks * 32);
#pragma unroll
        for (int p = 0; p < 4; p++) {
            uint32_t bh[4];
            ldsm4(bh, bBase + p * 4352 + ks * 32);
            mma16816(acc[2 * p],     ah, bh[0], bh[1]);
            mma16816(acc[2 * p + 1], ah, bh[2], bh[3]);
        }
    }

    // ---------------- epilogue 2: z + bias, BN partial sums ----------------
#pragma unroll
    for (int nt = 0; nt < 8; nt++) {
        int c0 = wc * 64 + nt * 8 + qcol * 2;
        float b0v = bblk[c0], b1v = bblk[c0 + 1];
        float z00 = acc[nt][0] + b0v, z01 = acc[nt][1] + b1v;
        float z10 = acc[nt][2] + b0v, z11 = acc[nt][3] + b1v;
        *(uint32_t*)(d_z + (size_t)(row0 + r0) * HID + c0)     = packh(z00, z01);
        *(uint32_t*)(d_z + (size_t)(row0 + r0 + 8) * HID + c0) = packh(z10, z11);
        float s0 = z00 + z10, s1 = z01 + z11;
        float q0 = z00 * z00 + z10 * z10, q1 = z01 * z01 + z11 * z11;
#pragma unroll
        for (int off = 4; off <= 16; off <<= 1) {
            s0 += __shfl_xor_sync(0xffffffffu, s0, off);
            s1 += __shfl_xor_sync(0xffffffffu, s1, off);
            q0 += __shfl_xor_sync(0xffffffffu, q0, off);
            q1 += __shfl_xor_sync(0xffffffffu, q1, off);
        }
        if (lane < 4) {
            wS[wr * 128 + c0] = s0; wS[wr * 128 + c0 + 1] = s1;
            wQ[wr * 128 + c0] = q0; wQ[wr * 128 + c0 + 1] = q1;
        }
    }
    __syncthreads();
    if (tid < 128) {
        float s = 0.f, q = 0.f;
#pragma unroll
        for (int g = 0; g < 8; g++) { s += wS[g * 128 + tid]; q += wQ[g * 128 + tid]; }
        d_colpart[blockIdx.x * 256 + tid] = s;
        d_colpart[blockIdx.x * 256 + 128 + tid] = q;
        d_mask[row0 + tid] = rowsq[tid];
    }
}

// ============================================================================
// kB: finalize BN stats -> scale/shift
// ============================================================================
__global__ void kB(const float* __restrict__ gamma, const float* __restrict__ beta) {
    __shared__ float rs[256], rq[256];
    int c = blockIdx.x;
    int tid = threadIdx.x;
    float s = 0.f, q = 0.f;
    for (int i = tid; i < NBLK_A; i += 256) {
        s += d_colpart[i * 256 + c];
        q += d_colpart[i * 256 + 128 + c];
    }
    rs[tid] = s; rq[tid] = q;
    __syncthreads();
    for (int st = 128; st > 0; st >>= 1) {
        if (tid < st) { rs[tid] += rs[tid + st]; rq[tid] += rq[tid + st]; }
        __syncthreads();
    }
    if (tid == 0) {
        float mu  = rs[0] * (1.f / (float)NROWS);
        float var = rq[0] * (1.f / (float)NROWS) - mu * mu;
        float sc  = gamma[c] * rsqrtf(var + 1e-5f);
        d_ss[c]       = sc;
        d_ss[128 + c] = beta[c] - mu * sc;
    }
}

// ============================================================================
// kC_mma: h2 = relu(bn(z)) + h; t = (h2@Wfc + b)*mask + gumbel
// ============================================================================
__global__ __launch_bounds__(256, 2) void kC_mma(
    const float* __restrict__ gumbel, const float* __restrict__ Wfc,
    const float* __restrict__ bfc)
{
    extern __shared__ char smem[];
    const uint32_t sb = smem_u32(smem);
    const int tid = threadIdx.x;
    const int lane = tid & 31;
    const int w = tid >> 5;
    const int row0 = blockIdx.x * 128;

    float* scs  = (float*)(smem + KC_SC);
    float* shs  = (float*)(smem + KC_SH);
    float* bfcs = (float*)(smem + KC_BFC);

#pragma unroll
    for (int u = 0; u < 4; u++) {
        int e = tid + u * 256;
        int k = e >> 3, j = e & 7;
        *(__half*)(smem + KC_WF + (j * 136 + k) * 2) = __float2half_rn(Wfc[e]);
    }
    if (tid < 128) { scs[tid] = d_ss[tid]; shs[tid] = d_ss[128 + tid]; }
    if (tid < 8)   bfcs[tid] = bfc[tid];
    __syncthreads();

    char* ah = smem + w * 4352;
    {
        const int c = lane * 4;
        float4 sc4 = *(float4*)(scs + c);
        float4 sh4 = *(float4*)(shs + c);
#pragma unroll
        for (int i = 0; i < 16; i++) {
            size_t g = (size_t)(row0 + w * 16 + i) * HID + c;
            uint2 zp = *(const uint2*)(d_z + g);
            uint2 hp = *(const uint2*)(d_h + g);
            float2 z0 = __half22float2(*(__half2*)&zp.x);
            float2 z1 = __half22float2(*(__half2*)&zp.y);
            float2 hh0 = __half22float2(*(__half2*)&hp.x);
            float2 hh1 = __half22float2(*(__half2*)&hp.y);
            float t0 = fmaxf(z0.x * sc4.x + sh4.x, 0.f) + hh0.x;
            float t1 = fmaxf(z0.y * sc4.y + sh4.y, 0.f) + hh0.y;
            float t2 = fmaxf(z1.x * sc4.z + sh4.z, 0.f) + hh1.x;
            float t3 = fmaxf(z1.y * sc4.w + sh4.w, 0.f) + hh1.y;
            *(uint2*)(ah + (i * 136 + c) * 2) =
                make_uint2(packh(t0, t1), packh(t2, t3));
        }
    }
    __syncwarp();

    float acc[4] = {0.f, 0.f, 0.f, 0.f};
    const uint32_t aB = sb + w * 4352 +
        (uint32_t)(((lane & 15) * 136 + ((lane >> 4) << 3)) * 2);
    const uint32_t bB = sb + KC_WF +
        (uint32_t)(((lane & 7) * 136 + ((lane >> 3) & 1) * 8) * 2);
#pragma unroll
    for (int ks = 0; ks < 8; ks++) {
        uint32_t ahf[4];
        ldsm4(ahf, aB + ks * 32);
        uint32_t bh0, bh1;
        ldsm2(bh0, bh1, bB + ks * 32);
        mma16816(acc, ahf, bh0, bh1);
    }

    const int qrow = lane >> 2, qcol = lane & 3;
    const int r0 = row0 + w * 16 + qrow;
    float m0 = d_mask[r0], m1 = d_mask[r0 + 8];
    float b0 = bfcs[qcol * 2], b1 = bfcs[qcol * 2 + 1];
    float2 g0 = *(const float2*)(gumbel + (size_t)r0 * 8 + qcol * 2);
    float2 g1 = *(const float2*)(gumbel + (size_t)(r0 + 8) * 8 + qcol * 2);
    *(float2*)(d_t + (size_t)r0 * 8 + qcol * 2) =
        make_float2((acc[0] + b0) * m0 + g0.x, (acc[1] + b1) * m0 + g0.y);
    *(float2*)(d_t + (size_t)(r0 + 8) * 8 + qcol * 2) =
        make_float2((acc[2] + b0) * m1 + g1.x, (acc[3] + b1) * m1 + g1.y);
}

// ============================================================================
// kD1: per-(b,chunk) partial softmax stats. grid = 256.
// ============================================================================
__global__ __launch_bounds__(256) void kD1() {
    __shared__ float wred[8][8];
    int b = blockIdx.x >> 3, ch = blockIdx.x & 7;
    int tid = threadIdx.x, lane = tid & 31, w = tid >> 5;
    size_t base = ((size_t)b * OO + ch * 512) * HH;

    float m[8];
#pragma unroll
    for (int h = 0; h < 8; h++) m[h] = -1e30f;
    for (int o = tid; o < 512; o += 256) {
        const float4* p = (const float4*)(d_t + base + (size_t)o * 8);
        float4 v0 = p[0], v1 = p[1];
        m[0] = fmaxf(m[0], v0.x); m[1] = fmaxf(m[1], v0.y);
        m[2] = fmaxf(m[2], v0.z); m[3] = fmaxf(m[3], v0.w);
        m[4] = fmaxf(m[4], v1.x); m[5] = fmaxf(m[5], v1.y);
        m[6] = fmaxf(m[6], v1.z); m[7] = fmaxf(m[7], v1.w);
    }
#pragma unroll
    for (int h = 0; h < 8; h++)
#pragma unroll
        for (int off = 16; off; off >>= 1)
            m[h] = fmaxf(m[h], __shfl_xor_sync(0xffffffffu, m[h], off));
    if (lane == 0)
#pragma unroll
        for (int h = 0; h < 8; h++) wred[w][h] = m[h];
    __syncthreads();
    float M[8];
#pragma unroll
    for (int h = 0; h < 8; h++) {
        float t = wred[0][h];
#pragma unroll
        for (int ww = 1; ww < 8; ww++) t = fmaxf(t, wred[ww][h]);
        M[h] = t;
    }
    __syncthreads();

    float s[8];
#pragma unroll
    for (int h = 0; h < 8; h++) s[h] = 0.f;
    for (int o = tid; o < 512; o += 256) {
        const float4* p = (const float4*)(d_t + base + (size_t)o * 8);
        float4 v0 = p[0], v1 = p[1];
        s[0] += expf(v0.x - M[0]); s[1] += expf(v0.y - M[1]);
        s[2] += expf(v0.z - M[2]); s[3] += expf(v0.w - M[3]);
        s[4] += expf(v1.x - M[4]); s[5] += expf(v1.y - M[5]);
        s[6] += expf(v1.z - M[6]); s[7] += expf(v1.w - M[7]);
    }
#pragma unroll
    for (int h = 0; h < 8; h++)
#pragma unroll
        for (int off = 16; off; off >>= 1)
            s[h] += __shfl_xor_sync(0xffffffffu, s[h], off);
    if (lane == 0)
#pragma unroll
        for (int h = 0; h < 8; h++) wred[w][h] = s[h];
    __syncthreads();
    if (tid < 8) {
        float t = 0.f;
#pragma unroll
        for (int ww = 0; ww < 8; ww++) t += wred[ww][tid];
        d_cmax[(b * 8 + ch) * HH + tid] = M[tid];
        d_csum[(b * 8 + ch) * HH + tid] = t;
    }
}

// ============================================================================
// kD2: combine chunk stats -> global M, invS per (b,h)
// ============================================================================
__global__ void kD2() {
    int b = blockIdx.x, h = threadIdx.x;
    if (h >= 8) return;
    float M = -1e30f;
#pragma unroll
    for (int ch = 0; ch < 8; ch++)
        M = fmaxf(M, d_cmax[(b * 8 + ch) * HH + h]);
    float S = 0.f;
#pragma unroll
    for (int ch = 0; ch < 8; ch++)
        S += d_csum[(b * 8 + ch) * HH + h] * expf(d_cmax[(b * 8 + ch) * HH + h] - M);
    d_M[b * HH + h] = M;
    d_invS[b * HH + h] = 1.f / S;
}

// ============================================================================
// kE: pooled partials, fused softmax normalization, og-groups reduced in smem
// before the gmem store (16 partials per b instead of 64).
// ============================================================================
__global__ __launch_bounds__(256) void kE(const float* __restrict__ x) {
    __shared__ float wsm[64 * 8];
    __shared__ float Ms[8], iSs[8];
    __shared__ float red[4 * 8 * 256];   // 32 KB: [og][h][f]
    int b = blockIdx.x >> 4, oc = blockIdx.x & 15;
    int tid = threadIdx.x;
    int fq = tid & 63;
    int og = tid >> 6;
    if (tid < 8)  Ms[tid] = d_M[b * HH + tid];
    if (tid >= 8 && tid < 16) iSs[tid - 8] = d_invS[b * HH + tid - 8];
    float acc[8][4];
#pragma unroll
    for (int h = 0; h < 8; h++)
#pragma unroll
        for (int j = 0; j < 4; j++) acc[h][j] = 0.f;
    int o0 = oc * 256;
    __syncthreads();

    for (int chunk = 0; chunk < 256; chunk += 64) {
        size_t wbase = ((size_t)b * OO + o0 + chunk) * 8;
        {
            int h0 = (tid * 2) & 7;
            float2 tv = *(const float2*)(d_t + wbase + tid * 2);
            wsm[tid * 2]     = expf(tv.x - Ms[h0])     * iSs[h0];
            wsm[tid * 2 + 1] = expf(tv.y - Ms[h0 + 1]) * iSs[h0 + 1];
        }
        __syncthreads();
#pragma unroll 4
        for (int t = 0; t < 16; t++) {
            int oo = og * 16 + t;
            float4 xv = *(const float4*)(x + ((size_t)b * OO + o0 + chunk + oo) * FF + fq * 4);
#pragma unroll
            for (int h = 0; h < 8; h++) {
                float wv = wsm[oo * 8 + h];
                acc[h][0] += wv * xv.x; acc[h][1] += wv * xv.y;
                acc[h][2] += wv * xv.z; acc[h][3] += wv * xv.w;
            }
        }
        __syncthreads();
    }
    // og reduction in smem
#pragma unroll
    for (int h = 0; h < 8; h++)
#pragma unroll
        for (int j = 0; j < 4; j++)
            red[(og * 8 + h) * 256 + fq * 4 + j] = acc[h][j];
    __syncthreads();
    int f = tid;
#pragma unroll
    for (int h = 0; h < 8; h++) {
        float s = red[h * 256 + f] + red[(8 + h) * 256 + f]
                + red[(16 + h) * 256 + f] + red[(24 + h) * 256 + f];
        d_partial[(((size_t)b * 16 + oc) * 8 + h) * FF + f] = s;
    }
}

// ============================================================================
// kF: final reduce over 16 partials
// ============================================================================
__global__ __launch_bounds__(256) void kF(float* __restrict__ out) {
    int bh = blockIdx.x;
    int b = bh >> 3, h = bh & 7;
    int f = threadIdx.x;
    float s = 0.f;
#pragma unroll
    for (int p = 0; p < 16; p++)
        s += d_partial[(((size_t)b * 16 + p) * 8 + h) * FF + f];
    out[(size_t)bh * FF + f] = s;
}

// ============================================================================
extern "C" void kernel_launch(void* const* d_in, const int* in_sizes, int n_in,
                              void* d_out, int out_size) {
    const float* x      = (const float*)d_in[0];
    const float* gumbel = (const float*)d_in[1];
    const float* Win    = (const float*)d_in[2];
    const float* bin    = (const float*)d_in[3];
    const float* Wblk   = (const float*)d_in[4];
    const float* bblk   = (const float*)d_in[5];
    const float* gamma  = (const float*)d_in[6];
    const float* beta   = (const float*)d_in[7];
    const float* Wfc    = (const float*)d_in[8];
    const float* bfc    = (const float*)d_in[9];
    float* out = (float*)d_out;

    cudaFuncSetAttribute(kA_mma, cudaFuncAttributeMaxDynamicSharedMemorySize, SMEM_TOTAL);
    cudaFuncSetAttribute(kC_mma, cudaFuncAttributeMaxDynamicSharedMemorySize, KC_SMEM);

    kW<<<128, 256>>>(Win, Wblk);
    kA_mma<<<NBLK_A, 512, SMEM_TOTAL>>>(x, bin, bblk);
    kB<<<128, 256>>>(gamma, beta);
    kC_mma<<<NROWS / 128, 256, KC_SMEM>>>(gumbel, Wfc, bfc);
    kD1<<<BB * 8, 256>>>();
    kD2<<<BB, 8>>>();
    kE<<<BB * 16, 256>>>(x);
    kF<<<BB * HH, 256>>>(out);
}

// round 14
// speedup vs baseline: 1.1227x; 1.1227x over previous
#include <cuda_runtime.h>
#include <cuda_fp16.h>
#include <cstdint>

#define NROWS 131072
#define BB 32
#define OO 4096
#define FF 256
#define HH 8
#define HID 128
#define NBLK_A 1024   // NROWS / 128

// ---------------- scratch (device globals) ----------------
__device__ __half d_h[NROWS * HID];
__device__ __half d_z[NROWS * HID];
__device__ float d_mask[NROWS];
__device__ float d_colpart[NBLK_A * 256];
__device__ float d_ss[256];
__device__ float d_t[NROWS * HH];
__device__ float d_cmax[BB * 8 * HH];
__device__ float d_csum[BB * 8 * HH];
__device__ float d_M[BB * HH];
__device__ float d_invS[BB * HH];
__device__ float d_partial[BB * 64 * HH * FF];
__device__ __half d_WinT[HID * FF];
__device__ __half d_WblkT[HID * HID];

// ---------------- smem layout for kA (bytes) ----------------
// A tile + 3 persistent B tiles (WinT k0, WinT k1, WblkT), 272 B row stride
#define TILE_BYTES 34816           // 128 * 272
#define AS    0
#define BS0   34816
#define BS1   69632
#define BS2   104448
#define ROWSQ 139264               // 128 floats
#define WSUM  139776               // 8*128 floats
#define WSQ   143872               // 8*128 floats
#define SMEM_TOTAL 147968          // 1 CTA/SM, L1 keeps ~80KB

// ---------------- smem layout for kC (bytes) ----------------
#define KC_WF  34816               // 8 x 136 fp16
#define KC_SC  36992
#define KC_SH  37504
#define KC_BFC 38016
#define KC_SMEM 38048

// ---------------- helpers ----------------
__device__ __forceinline__ uint32_t smem_u32(const void* p) {
    uint32_t a;
    asm("{ .reg .u64 t; cvta.to.shared.u64 t, %1; cvt.u32.u64 %0, t; }" : "=r"(a) : "l"(p));
    return a;
}
__device__ __forceinline__ void ldsm4(uint32_t* r, uint32_t addr) {
    asm volatile("ldmatrix.sync.aligned.m8n8.x4.shared.b16 {%0,%1,%2,%3}, [%4];"
        : "=r"(r[0]), "=r"(r[1]), "=r"(r[2]), "=r"(r[3]) : "r"(addr));
}
__device__ __forceinline__ void ldsm2(uint32_t& r0, uint32_t& r1, uint32_t addr) {
    asm volatile("ldmatrix.sync.aligned.m8n8.x2.shared.b16 {%0,%1}, [%2];"
        : "=r"(r0), "=r"(r1) : "r"(addr));
}
__device__ __forceinline__ void mma16816(float* c, const uint32_t* a, uint32_t b0, uint32_t b1) {
    asm volatile("mma.sync.aligned.m16n8k16.row.col.f32.f16.f16.f32 "
        "{%0,%1,%2,%3}, {%4,%5,%6,%7}, {%8,%9}, {%0,%1,%2,%3};"
        : "+f"(c[0]), "+f"(c[1]), "+f"(c[2]), "+f"(c[3])
        : "r"(a[0]), "r"(a[1]), "r"(a[2]), "r"(a[3]), "r"(b0), "r"(b1));
}
__device__ __forceinline__ uint32_t packh(float a, float b) {
    __half2 hp = __floats2half2_rn(a, b);
    return *reinterpret_cast<uint32_t*>(&hp);
}

// ============================================================================
// kW: convert weights to fp16, transposed to [N][K]
// ============================================================================
__global__ void kW(const float* __restrict__ Win, const float* __restrict__ Wblk) {
    int e = blockIdx.x * 256 + threadIdx.x;
    if (e < HID * FF) {
        int n = e >> 8, k = e & 255;
        d_WinT[e] = __float2half_rn(Win[(size_t)k * HID + n]);
    }
    if (e < HID * HID) {
        int n = e >> 7, k = e & 127;
        d_WblkT[e] = __float2half_rn(Wblk[(size_t)k * HID + n]);
    }
}

// ============================================================================
// kA_mma: h = relu(x@Win+b); z = h@Wblk+b; BN col partials; row mask
// 128 rows/CTA, 16 warps (warp = 16 rows x 64 cols). fp16 x fp16 MMA.
// All three B tiles preloaded once at entry (overlaps x chunk-0 DRAM wait);
// no mid-kernel B loads, 7 syncs instead of 9.
// ============================================================================
__global__ __launch_bounds__(512, 1) void kA_mma(
    const float* __restrict__ x, const float* __restrict__ bin,
    const float* __restrict__ bblk)
{
    extern __shared__ char smem[];
    const uint32_t sb = smem_u32(smem);
    const int tid = threadIdx.x;
    const int lane = tid & 31;
    const int w = tid >> 5;
    const int wr = w >> 1;        // row group 0..7 (16 rows each)
    const int wc = w & 1;         // col half 0..1 (64 cols each)
    const int row0 = blockIdx.x * 128;

    float* rowsq = (float*)(smem + ROWSQ);
    float* wS = (float*)(smem + WSUM);
    float* wQ = (float*)(smem + WSQ);
    if (tid < 128) rowsq[tid] = 0.f;

    // ---- persistent B preload: WinT k0, WinT k1, WblkT (L2-hot) ----
#pragma unroll
    for (int i = 0; i < 4; i++) {
        int idx = tid + i * 512;
        int n = idx >> 4, q = idx & 15;
        uint32_t doff = (uint32_t)(n * 272 + q * 16);
        *(uint4*)(smem + BS0 + doff) = *(const uint4*)(d_WinT + (size_t)n * FF + q * 8);
        *(uint4*)(smem + BS1 + doff) = *(const uint4*)(d_WinT + (size_t)n * FF + 128 + q * 8);
        *(uint4*)(smem + BS2 + doff) = *(const uint4*)(d_WblkT + (size_t)n * HID + q * 8);
    }

    float acc[8][4];
#pragma unroll
    for (int nt = 0; nt < 8; nt++)
#pragma unroll
        for (int j = 0; j < 4; j++) acc[nt][j] = 0.f;

    // ldmatrix lane bases
    const uint32_t aBase = sb + AS +
        (uint32_t)((wr * 16 + (lane & 15)) * 272 + ((lane >> 4) << 3) * 2);
    const uint32_t laneB = (uint32_t)(wc * 64 * 272 +
        ((lane & 7) + ((lane >> 4) << 3)) * 272 + ((lane >> 3) & 1) * 16);

    // ---- x chunk 0 -> fp16 A + row-nonzero vote (overlaps B LDGs above) ----
#pragma unroll
    for (int i = 0; i < 8; i++) {
        int idx = tid + i * 512;
        int r = idx >> 5, c4 = idx & 31;
        float4 v = *(const float4*)(x + (size_t)(row0 + r) * FF + c4 * 4);
        int nz = (v.x != 0.f) | (v.y != 0.f) | (v.z != 0.f) | (v.w != 0.f);
        if (__any_sync(0xffffffffu, nz) && lane == 0) rowsq[r] = 1.f;
        *(uint2*)(smem + AS + (uint32_t)(r * 272 + c4 * 8)) =
            make_uint2(packh(v.x, v.y), packh(v.z, v.w));
    }
    __syncthreads();

    // ---- MMA chunk 0 (B = BS0) ----
#pragma unroll
    for (int ks = 0; ks < 8; ks++) {
        uint32_t ah[4];
        ldsm4(ah, aBase + ks * 32);
#pragma unroll
        for (int p = 0; p < 4; p++) {
            uint32_t bh[4];
            ldsm4(bh, sb + BS0 + laneB + p * 4352 + ks * 32);
            mma16816(acc[2 * p],     ah, bh[0], bh[1]);
            mma16816(acc[2 * p + 1], ah, bh[2], bh[3]);
        }
    }
    __syncthreads();   // drain chunk-0 A reads before overwrite

    // ---- x chunk 1 -> fp16 A ----
#pragma unroll
    for (int i = 0; i < 8; i++) {
        int idx = tid + i * 512;
        int r = idx >> 5, c4 = idx & 31;
        float4 v = *(const float4*)(x + (size_t)(row0 + r) * FF + 128 + c4 * 4);
        int nz = (v.x != 0.f) | (v.y != 0.f) | (v.z != 0.f) | (v.w != 0.f);
        if (__any_sync(0xffffffffu, nz) && lane == 0) rowsq[r] = 1.f;
        *(uint2*)(smem + AS + (uint32_t)(r * 272 + c4 * 8)) =
            make_uint2(packh(v.x, v.y), packh(v.z, v.w));
    }
    __syncthreads();

    // ---- MMA chunk 1 (B = BS1, already resident) ----
#pragma unroll
    for (int ks = 0; ks < 8; ks++) {
        uint32_t ah[4];
        ldsm4(ah, aBase + ks * 32);
#pragma unroll
        for (int p = 0; p < 4; p++) {
            uint32_t bh[4];
            ldsm4(bh, sb + BS1 + laneB + p * 4352 + ks * 32);
            mma16816(acc[2 * p],     ah, bh[0], bh[1]);
            mma16816(acc[2 * p + 1], ah, bh[2], bh[3]);
        }
    }
    // RACE FIX: both col-half warps read all k of the shared A rows above;
    // epilogue 1 overwrites those rows with h. Drain block-wide first.
    __syncthreads();

    // ---------------- epilogue 1: h = relu(acc + bin) ----------------
    const int qrow = lane >> 2, qcol = lane & 3;
    const int r0 = wr * 16 + qrow;
#pragma unroll
    for (int nt = 0; nt < 8; nt++) {
        int c0 = wc * 64 + nt * 8 + qcol * 2;
        float b0v = bin[c0], b1v = bin[c0 + 1];
        float h00 = fmaxf(acc[nt][0] + b0v, 0.f);
        float h01 = fmaxf(acc[nt][1] + b1v, 0.f);
        float h10 = fmaxf(acc[nt][2] + b0v, 0.f);
        float h11 = fmaxf(acc[nt][3] + b1v, 0.f);
        uint32_t p00 = packh(h00, h01);
        uint32_t p10 = packh(h10, h11);
        *(uint32_t*)(d_h + (size_t)(row0 + r0) * HID + c0)     = p00;
        *(uint32_t*)(d_h + (size_t)(row0 + r0 + 8) * HID + c0) = p10;
        *(uint32_t*)(smem + AS + (r0 * 136 + c0) * 2)       = p00;
        *(uint32_t*)(smem + AS + ((r0 + 8) * 136 + c0) * 2) = p10;
        acc[nt][0] = acc[nt][1] = acc[nt][2] = acc[nt][3] = 0.f;
    }
    __syncthreads();  // h tile ready; WblkT already resident in BS2

    // ---------------- GEMM2: z = h @ Wblk, K=128 ----------------
#pragma unroll
    for (int ks = 0; ks < 8; ks++) {
        uint32_t ah[4];
        ldsm4(ah, aBase + ks * 32);
#pragma unroll
        for (int p = 0; p < 4; p++) {
            uint32_t bh[4];
            ldsm4(bh, sb + BS2 + laneB + p * 4352 + ks * 32);
            mma16816(acc[2 * p],     ah, bh[0], bh[1]);
            mma16816(acc[2 * p + 1], ah, bh[2], bh[3]);
        }
    }

    // ---------------- epilogue 2: z + bias, BN partial sums ----------------
#pragma unroll
    for (int nt = 0; nt < 8; nt++) {
        int c0 = wc * 64 + nt * 8 + qcol * 2;
        float b0v = bblk[c0], b1v = bblk[c0 + 1];
        float z00 = acc[nt][0] + b0v, z01 = acc[nt][1] + b1v;
        float z10 = acc[nt][2] + b0v, z11 = acc[nt][3] + b1v;
        *(uint32_t*)(d_z + (size_t)(row0 + r0) * HID + c0)     = packh(z00, z01);
        *(uint32_t*)(d_z + (size_t)(row0 + r0 + 8) * HID + c0) = packh(z10, z11);
        float s0 = z00 + z10, s1 = z01 + z11;
        float q0 = z00 * z00 + z10 * z10, q1 = z01 * z01 + z11 * z11;
#pragma unroll
        for (int off = 4; off <= 16; off <<= 1) {
            s0 += __shfl_xor_sync(0xffffffffu, s0, off);
            s1 += __shfl_xor_sync(0xffffffffu, s1, off);
            q0 += __shfl_xor_sync(0xffffffffu, q0, off);
            q1 += __shfl_xor_sync(0xffffffffu, q1, off);
        }
        if (lane < 4) {
            wS[wr * 128 + c0] = s0; wS[wr * 128 + c0 + 1] = s1;
            wQ[wr * 128 + c0] = q0; wQ[wr * 128 + c0 + 1] = q1;
        }
    }
    __syncthreads();
    if (tid < 128) {
        float s = 0.f, q = 0.f;
#pragma unroll
        for (int g = 0; g < 8; g++) { s += wS[g * 128 + tid]; q += wQ[g * 128 + tid]; }
        d_colpart[blockIdx.x * 256 + tid] = s;
        d_colpart[blockIdx.x * 256 + 128 + tid] = q;
        d_mask[row0 + tid] = rowsq[tid];
    }
}

// ============================================================================
// kB: finalize BN stats -> scale/shift
// ============================================================================
__global__ void kB(const float* __restrict__ gamma, const float* __restrict__ beta) {
    __shared__ float rs[256], rq[256];
    int c = blockIdx.x;
    int tid = threadIdx.x;
    float s = 0.f, q = 0.f;
    for (int i = tid; i < NBLK_A; i += 256) {
        s += d_colpart[i * 256 + c];
        q += d_colpart[i * 256 + 128 + c];
    }
    rs[tid] = s; rq[tid] = q;
    __syncthreads();
    for (int st = 128; st > 0; st >>= 1) {
        if (tid < st) { rs[tid] += rs[tid + st]; rq[tid] += rq[tid + st]; }
        __syncthreads();
    }
    if (tid == 0) {
        float mu  = rs[0] * (1.f / (float)NROWS);
        float var = rq[0] * (1.f / (float)NROWS) - mu * mu;
        float sc  = gamma[c] * rsqrtf(var + 1e-5f);
        d_ss[c]       = sc;
        d_ss[128 + c] = beta[c] - mu * sc;
    }
}

// ============================================================================
// kC_mma: h2 = relu(bn(z)) + h; t = (h2@Wfc + b)*mask + gumbel
// ============================================================================
__global__ __launch_bounds__(256, 2) void kC_mma(
    const float* __restrict__ gumbel, const float* __restrict__ Wfc,
    const float* __restrict__ bfc)
{
    extern __shared__ char smem[];
    const uint32_t sb = smem_u32(smem);
    const int tid = threadIdx.x;
    const int lane = tid & 31;
    const int w = tid >> 5;
    const int row0 = blockIdx.x * 128;

    float* scs  = (float*)(smem + KC_SC);
    float* shs  = (float*)(smem + KC_SH);
    float* bfcs = (float*)(smem + KC_BFC);

#pragma unroll
    for (int u = 0; u < 4; u++) {
        int e = tid + u * 256;
        int k = e >> 3, j = e & 7;
        *(__half*)(smem + KC_WF + (j * 136 + k) * 2) = __float2half_rn(Wfc[e]);
    }
    if (tid < 128) { scs[tid] = d_ss[tid]; shs[tid] = d_ss[128 + tid]; }
    if (tid < 8)   bfcs[tid] = bfc[tid];
    __syncthreads();

    char* ah = smem + w * 4352;
    {
        const int c = lane * 4;
        float4 sc4 = *(float4*)(scs + c);
        float4 sh4 = *(float4*)(shs + c);
#pragma unroll
        for (int i = 0; i < 16; i++) {
            size_t g = (size_t)(row0 + w * 16 + i) * HID + c;
            uint2 zp = *(const uint2*)(d_z + g);
            uint2 hp = *(const uint2*)(d_h + g);
            float2 z0 = __half22float2(*(__half2*)&zp.x);
            float2 z1 = __half22float2(*(__half2*)&zp.y);
            float2 hh0 = __half22float2(*(__half2*)&hp.x);
            float2 hh1 = __half22float2(*(__half2*)&hp.y);
            float t0 = fmaxf(z0.x * sc4.x + sh4.x, 0.f) + hh0.x;
            float t1 = fmaxf(z0.y * sc4.y + sh4.y, 0.f) + hh0.y;
            float t2 = fmaxf(z1.x * sc4.z + sh4.z, 0.f) + hh1.x;
            float t3 = fmaxf(z1.y * sc4.w + sh4.w, 0.f) + hh1.y;
            *(uint2*)(ah + (i * 136 + c) * 2) =
                make_uint2(packh(t0, t1), packh(t2, t3));
        }
    }
    __syncwarp();

    float acc[4] = {0.f, 0.f, 0.f, 0.f};
    const uint32_t aB = sb + w * 4352 +
        (uint32_t)(((lane & 15) * 136 + ((lane >> 4) << 3)) * 2);
    const uint32_t bB = sb + KC_WF +
        (uint32_t)(((lane & 7) * 136 + ((lane >> 3) & 1) * 8) * 2);
#pragma unroll
    for (int ks = 0; ks < 8; ks++) {
        uint32_t ahf[4];
        ldsm4(ahf, aB + ks * 32);
        uint32_t bh0, bh1;
        ldsm2(bh0, bh1, bB + ks * 32);
        mma16816(acc, ahf, bh0, bh1);
    }

    const int qrow = lane >> 2, qcol = lane & 3;
    const int r0 = row0 + w * 16 + qrow;
    float m0 = d_mask[r0], m1 = d_mask[r0 + 8];
    float b0 = bfcs[qcol * 2], b1 = bfcs[qcol * 2 + 1];
    float2 g0 = *(const float2*)(gumbel + (size_t)r0 * 8 + qcol * 2);
    float2 g1 = *(const float2*)(gumbel + (size_t)(r0 + 8) * 8 + qcol * 2);
    *(float2*)(d_t + (size_t)r0 * 8 + qcol * 2) =
        make_float2((acc[0] + b0) * m0 + g0.x, (acc[1] + b1) * m0 + g0.y);
    *(float2*)(d_t + (size_t)(r0 + 8) * 8 + qcol * 2) =
        make_float2((acc[2] + b0) * m1 + g1.x, (acc[3] + b1) * m1 + g1.y);
}

// ============================================================================
// kD1: per-(b,chunk) partial softmax stats. grid = 256.
// ============================================================================
__global__ __launch_bounds__(256) void kD1() {
    __shared__ float wred[8][8];
    int b = blockIdx.x >> 3, ch = blockIdx.x & 7;
    int tid = threadIdx.x, lane = tid & 31, w = tid >> 5;
    size_t base = ((size_t)b * OO + ch * 512) * HH;

    float m[8];
#pragma unroll
    for (int h = 0; h < 8; h++) m[h] = -1e30f;
    for (int o = tid; o < 512; o += 256) {
        const float4* p = (const float4*)(d_t + base + (size_t)o * 8);
        float4 v0 = p[0], v1 = p[1];
        m[0] = fmaxf(m[0], v0.x); m[1] = fmaxf(m[1], v0.y);
        m[2] = fmaxf(m[2], v0.z); m[3] = fmaxf(m[3], v0.w);
        m[4] = fmaxf(m[4], v1.x); m[5] = fmaxf(m[5], v1.y);
        m[6] = fmaxf(m[6], v1.z); m[7] = fmaxf(m[7], v1.w);
    }
#pragma unroll
    for (int h = 0; h < 8; h++)
#pragma unroll
        for (int off = 16; off; off >>= 1)
            m[h] = fmaxf(m[h], __shfl_xor_sync(0xffffffffu, m[h], off));
    if (lane == 0)
#pragma unroll
        for (int h = 0; h < 8; h++) wred[w][h] = m[h];
    __syncthreads();
    float M[8];
#pragma unroll
    for (int h = 0; h < 8; h++) {
        float t = wred[0][h];
#pragma unroll
        for (int ww = 1; ww < 8; ww++) t = fmaxf(t, wred[ww][h]);
        M[h] = t;
    }
    __syncthreads();

    float s[8];
#pragma unroll
    for (int h = 0; h < 8; h++) s[h] = 0.f;
    for (int o = tid; o < 512; o += 256) {
        const float4* p = (const float4*)(d_t + base + (size_t)o * 8);
        float4 v0 = p[0], v1 = p[1];
        s[0] += expf(v0.x - M[0]); s[1] += expf(v0.y - M[1]);
        s[2] += expf(v0.z - M[2]); s[3] += expf(v0.w - M[3]);
        s[4] += expf(v1.x - M[4]); s[5] += expf(v1.y - M[5]);
        s[6] += expf(v1.z - M[6]); s[7] += expf(v1.w - M[7]);
    }
#pragma unroll
    for (int h = 0; h < 8; h++)
#pragma unroll
        for (int off = 16; off; off >>= 1)
            s[h] += __shfl_xor_sync(0xffffffffu, s[h], off);
    if (lane == 0)
#pragma unroll
        for (int h = 0; h < 8; h++) wred[w][h] = s[h];
    __syncthreads();
    if (tid < 8) {
        float t = 0.f;
#pragma unroll
        for (int ww = 0; ww < 8; ww++) t += wred[ww][tid];
        d_cmax[(b * 8 + ch) * HH + tid] = M[tid];
        d_csum[(b * 8 + ch) * HH + tid] = t;
    }
}

// ============================================================================
// kD2: combine chunk stats -> global M, invS per (b,h)
// ============================================================================
__global__ void kD2() {
    int b = blockIdx.x, h = threadIdx.x;
    if (h >= 8) return;
    float M = -1e30f;
#pragma unroll
    for (int ch = 0; ch < 8; ch++)
        M = fmaxf(M, d_cmax[(b * 8 + ch) * HH + h]);
    float S = 0.f;
#pragma unroll
    for (int ch = 0; ch < 8; ch++)
        S += d_csum[(b * 8 + ch) * HH + h] * expf(d_cmax[(b * 8 + ch) * HH + h] - M);
    d_M[b * HH + h] = M;
    d_invS[b * HH + h] = 1.f / S;
}

// ============================================================================
// kE: pooled partials with fused softmax normalization (round-12 version)
// ============================================================================
__global__ __launch_bounds__(256) void kE(const float* __restrict__ x) {
    __shared__ float wsm[64 * 8];
    __shared__ float Ms[8], iSs[8];
    int b = blockIdx.x >> 4, oc = blockIdx.x & 15;
    int tid = threadIdx.x;
    int fq = tid & 63;
    int og = tid >> 6;
    if (tid < 8)  Ms[tid] = d_M[b * HH + tid];
    if (tid >= 8 && tid < 16) iSs[tid - 8] = d_invS[b * HH + tid - 8];
    float acc[8][4];
#pragma unroll
    for (int h = 0; h < 8; h++)
#pragma unroll
        for (int j = 0; j < 4; j++) acc[h][j] = 0.f;
    int o0 = oc * 256;
    __syncthreads();

    for (int chunk = 0; chunk < 256; chunk += 64) {
        size_t wbase = ((size_t)b * OO + o0 + chunk) * 8;
        {
            int h0 = (tid * 2) & 7;
            float2 tv = *(const float2*)(d_t + wbase + tid * 2);
            wsm[tid * 2]     = expf(tv.x - Ms[h0])     * iSs[h0];
            wsm[tid * 2 + 1] = expf(tv.y - Ms[h0 + 1]) * iSs[h0 + 1];
        }
        __syncthreads();
#pragma unroll 4
        for (int t = 0; t < 16; t++) {
            int oo = og * 16 + t;
            float4 xv = *(const float4*)(x + ((size_t)b * OO + o0 + chunk + oo) * FF + fq * 4);
#pragma unroll
            for (int h = 0; h < 8; h++) {
                float wv = wsm[oo * 8 + h];
                acc[h][0] += wv * xv.x; acc[h][1] += wv * xv.y;
                acc[h][2] += wv * xv.z; acc[h][3] += wv * xv.w;
            }
        }
        __syncthreads();
    }
#pragma unroll
    for (int h = 0; h < 8; h++)
        *(float4*)(d_partial + (((size_t)b * 64 + oc * 4 + og) * 8 + h) * FF + fq * 4) =
            make_float4(acc[h][0], acc[h][1], acc[h][2], acc[h][3]);
}

// ============================================================================
// kF: final reduce over 64 partials
// ============================================================================
__global__ __launch_bounds__(256) void kF(float* __restrict__ out) {
    int bh = blockIdx.x;
    int b = bh >> 3, h = bh & 7;
    int f = threadIdx.x;
    float s = 0.f;
#pragma unroll
    for (int p = 0; p < 64; p++)
        s += d_partial[(((size_t)b * 64 + p) * 8 + h) * FF + f];
    out[(size_t)bh * FF + f] = s;
}

// ============================================================================
extern "C" void kernel_launch(void* const* d_in, const int* in_sizes, int n_in,
                              void* d_out, int out_size) {
    const float* x      = (const float*)d_in[0];
    const float* gumbel = (const float*)d_in[1];
    const float* Win    = (const float*)d_in[2];
    const float* bin    = (const float*)d_in[3];
    const float* Wblk   = (const float*)d_in[4];
    const float* bblk   = (const float*)d_in[5];
    const float* gamma  = (const float*)d_in[6];
    const float* beta   = (const float*)d_in[7];
    const float* Wfc    = (const float*)d_in[8];
    const float* bfc    = (const float*)d_in[9];
    float* out = (float*)d_out;

    cudaFuncSetAttribute(kA_mma, cudaFuncAttributeMaxDynamicSharedMemorySize, SMEM_TOTAL);
    cudaFuncSetAttribute(kC_mma, cudaFuncAttributeMaxDynamicSharedMemorySize, KC_SMEM);

    kW<<<128, 256>>>(Win, Wblk);
    kA_mma<<<NBLK_A, 512, SMEM_TOTAL>>>(x, bin, bblk);
    kB<<<128, 256>>>(gamma, beta);
    kC_mma<<<NROWS / 128, 256, KC_SMEM>>>(gumbel, Wfc, bfc);
    kD1<<<BB * 8, 256>>>();
    kD2<<<BB, 8>>>();
    kE<<<BB * 16, 256>>>(x);
    kF<<<BB * HH, 256>>>(out);
}

// round 15
// speedup vs baseline: 1.1232x; 1.0004x over previous
#include <cuda_runtime.h>
#include <cuda_fp16.h>
#include <cstdint>

#define NROWS 131072
#define BB 32
#define OO 4096
#define FF 256
#define HH 8
#define HID 128
#define NBLK_A 1024   // NROWS / 128

// ---------------- scratch (device globals) ----------------
__device__ __half d_h[NROWS * HID];
__device__ __half d_z[NROWS * HID];
__device__ float d_mask[NROWS];
__device__ float d_colpart[NBLK_A * 256];
__device__ float d_ss[256];
__device__ float d_t[NROWS * HH];
__device__ float d_cmax[1024 * HH];     // per kC-block stats (1024 chunks)
__device__ float d_csum[1024 * HH];
__device__ float d_M[BB * HH];
__device__ float d_invS[BB * HH];
__device__ float d_partial[BB * 64 * HH * FF];
__device__ __half d_WinT[HID * FF];
__device__ __half d_WblkT[HID * HID];

// ---------------- smem layout for kA (bytes) ----------------
#define TILE_BYTES 34816           // 128 * 272
#define AS    0
#define BS0   34816
#define BS1   69632
#define BS2   104448
#define ROWSQ 139264               // 128 floats
#define WSUM  139776               // 8*128 floats
#define WSQ   143872               // 8*128 floats
#define SMEM_TOTAL 147968          // 1 CTA/SM

// ---------------- smem layout for kC (bytes) ----------------
#define KC_WF   34816              // 8 x 136 fp16
#define KC_SC   36992
#define KC_SH   37504
#define KC_BFC  38016
#define KC_STM  38048              // 64 floats: per-warp per-h max
#define KC_STS  38304              // 64 floats: per-warp per-h sumexp
#define KC_MB   38560              // 8 floats: block max per h
#define KC_SMEM 38592

// ---------------- helpers ----------------
__device__ __forceinline__ uint32_t smem_u32(const void* p) {
    uint32_t a;
    asm("{ .reg .u64 t; cvta.to.shared.u64 t, %1; cvt.u32.u64 %0, t; }" : "=r"(a) : "l"(p));
    return a;
}
__device__ __forceinline__ void ldsm4(uint32_t* r, uint32_t addr) {
    asm volatile("ldmatrix.sync.aligned.m8n8.x4.shared.b16 {%0,%1,%2,%3}, [%4];"
        : "=r"(r[0]), "=r"(r[1]), "=r"(r[2]), "=r"(r[3]) : "r"(addr));
}
__device__ __forceinline__ void ldsm2(uint32_t& r0, uint32_t& r1, uint32_t addr) {
    asm volatile("ldmatrix.sync.aligned.m8n8.x2.shared.b16 {%0,%1}, [%2];"
        : "=r"(r0), "=r"(r1) : "r"(addr));
}
__device__ __forceinline__ void mma16816(float* c, const uint32_t* a, uint32_t b0, uint32_t b1) {
    asm volatile("mma.sync.aligned.m16n8k16.row.col.f32.f16.f16.f32 "
        "{%0,%1,%2,%3}, {%4,%5,%6,%7}, {%8,%9}, {%0,%1,%2,%3};"
        : "+f"(c[0]), "+f"(c[1]), "+f"(c[2]), "+f"(c[3])
        : "r"(a[0]), "r"(a[1]), "r"(a[2]), "r"(a[3]), "r"(b0), "r"(b1));
}
__device__ __forceinline__ uint32_t packh(float a, float b) {
    __half2 hp = __floats2half2_rn(a, b);
    return *reinterpret_cast<uint32_t*>(&hp);
}

// ============================================================================
// kW: convert weights to fp16, transposed to [N][K]
// ============================================================================
__global__ void kW(const float* __restrict__ Win, const float* __restrict__ Wblk) {
    int e = blockIdx.x * 256 + threadIdx.x;
    if (e < HID * FF) {
        int n = e >> 8, k = e & 255;
        d_WinT[e] = __float2half_rn(Win[(size_t)k * HID + n]);
    }
    if (e < HID * HID) {
        int n = e >> 7, k = e & 127;
        d_WblkT[e] = __float2half_rn(Wblk[(size_t)k * HID + n]);
    }
}

// ============================================================================
// kA_mma: h = relu(x@Win+b); z = h@Wblk+b; BN col partials; row mask
// (round-14 version: all 3 B tiles preloaded once at entry)
// ============================================================================
__global__ __launch_bounds__(512, 1) void kA_mma(
    const float* __restrict__ x, const float* __restrict__ bin,
    const float* __restrict__ bblk)
{
    extern __shared__ char smem[];
    const uint32_t sb = smem_u32(smem);
    const int tid = threadIdx.x;
    const int lane = tid & 31;
    const int w = tid >> 5;
    const int wr = w >> 1;
    const int wc = w & 1;
    const int row0 = blockIdx.x * 128;

    float* rowsq = (float*)(smem + ROWSQ);
    float* wS = (float*)(smem + WSUM);
    float* wQ = (float*)(smem + WSQ);
    if (tid < 128) rowsq[tid] = 0.f;

    // persistent B preload: WinT k0, WinT k1, WblkT
#pragma unroll
    for (int i = 0; i < 4; i++) {
        int idx = tid + i * 512;
        int n = idx >> 4, q = idx & 15;
        uint32_t doff = (uint32_t)(n * 272 + q * 16);
        *(uint4*)(smem + BS0 + doff) = *(const uint4*)(d_WinT + (size_t)n * FF + q * 8);
        *(uint4*)(smem + BS1 + doff) = *(const uint4*)(d_WinT + (size_t)n * FF + 128 + q * 8);
        *(uint4*)(smem + BS2 + doff) = *(const uint4*)(d_WblkT + (size_t)n * HID + q * 8);
    }

    float acc[8][4];
#pragma unroll
    for (int nt = 0; nt < 8; nt++)
#pragma unroll
        for (int j = 0; j < 4; j++) acc[nt][j] = 0.f;

    const uint32_t aBase = sb + AS +
        (uint32_t)((wr * 16 + (lane & 15)) * 272 + ((lane >> 4) << 3) * 2);
    const uint32_t laneB = (uint32_t)(wc * 64 * 272 +
        ((lane & 7) + ((lane >> 4) << 3)) * 272 + ((lane >> 3) & 1) * 16);

    // x chunk 0 -> fp16 A + row-nonzero vote
#pragma unroll
    for (int i = 0; i < 8; i++) {
        int idx = tid + i * 512;
        int r = idx >> 5, c4 = idx & 31;
        float4 v = *(const float4*)(x + (size_t)(row0 + r) * FF + c4 * 4);
        int nz = (v.x != 0.f) | (v.y != 0.f) | (v.z != 0.f) | (v.w != 0.f);
        if (__any_sync(0xffffffffu, nz) && lane == 0) rowsq[r] = 1.f;
        *(uint2*)(smem + AS + (uint32_t)(r * 272 + c4 * 8)) =
            make_uint2(packh(v.x, v.y), packh(v.z, v.w));
    }
    __syncthreads();

    // MMA chunk 0 (B = BS0)
#pragma unroll
    for (int ks = 0; ks < 8; ks++) {
        uint32_t ah[4];
        ldsm4(ah, aBase + ks * 32);
#pragma unroll
        for (int p = 0; p < 4; p++) {
            uint32_t bh[4];
            ldsm4(bh, sb + BS0 + laneB + p * 4352 + ks * 32);
            mma16816(acc[2 * p],     ah, bh[0], bh[1]);
            mma16816(acc[2 * p + 1], ah, bh[2], bh[3]);
        }
    }
    __syncthreads();

    // x chunk 1 -> fp16 A
#pragma unroll
    for (int i = 0; i < 8; i++) {
        int idx = tid + i * 512;
        int r = idx >> 5, c4 = idx & 31;
        float4 v = *(const float4*)(x + (size_t)(row0 + r) * FF + 128 + c4 * 4);
        int nz = (v.x != 0.f) | (v.y != 0.f) | (v.z != 0.f) | (v.w != 0.f);
        if (__any_sync(0xffffffffu, nz) && lane == 0) rowsq[r] = 1.f;
        *(uint2*)(smem + AS + (uint32_t)(r * 272 + c4 * 8)) =
            make_uint2(packh(v.x, v.y), packh(v.z, v.w));
    }
    __syncthreads();

    // MMA chunk 1 (B = BS1)
#pragma unroll
    for (int ks = 0; ks < 8; ks++) {
        uint32_t ah[4];
        ldsm4(ah, aBase + ks * 32);
#pragma unroll
        for (int p = 0; p < 4; p++) {
            uint32_t bh[4];
            ldsm4(bh, sb + BS1 + laneB + p * 4352 + ks * 32);
            mma16816(acc[2 * p],     ah, bh[0], bh[1]);
            mma16816(acc[2 * p + 1], ah, bh[2], bh[3]);
        }
    }
    // RACE FIX: drain all GEMM1 A reads before overwriting rows with h
    __syncthreads();

    // epilogue 1: h = relu(acc + bin)
    const int qrow = lane >> 2, qcol = lane & 3;
    const int r0 = wr * 16 + qrow;
#pragma unroll
    for (int nt = 0; nt < 8; nt++) {
        int c0 = wc * 64 + nt * 8 + qcol * 2;
        float b0v = bin[c0], b1v = bin[c0 + 1];
        float h00 = fmaxf(acc[nt][0] + b0v, 0.f);
        float h01 = fmaxf(acc[nt][1] + b1v, 0.f);
        float h10 = fmaxf(acc[nt][2] + b0v, 0.f);
        float h11 = fmaxf(acc[nt][3] + b1v, 0.f);
        uint32_t p00 = packh(h00, h01);
        uint32_t p10 = packh(h10, h11);
        *(uint32_t*)(d_h + (size_t)(row0 + r0) * HID + c0)     = p00;
        *(uint32_t*)(d_h + (size_t)(row0 + r0 + 8) * HID + c0) = p10;
        *(uint32_t*)(smem + AS + (r0 * 136 + c0) * 2)       = p00;
        *(uint32_t*)(smem + AS + ((r0 + 8) * 136 + c0) * 2) = p10;
        acc[nt][0] = acc[nt][1] = acc[nt][2] = acc[nt][3] = 0.f;
    }
    __syncthreads();

    // GEMM2: z = h @ Wblk (B = BS2, resident)
#pragma unroll
    for (int ks = 0; ks < 8; ks++) {
        uint32_t ah[4];
        ldsm4(ah, aBase + ks * 32);
#pragma unroll
        for (int p = 0; p < 4; p++) {
            uint32_t bh[4];
            ldsm4(bh, sb + BS2 + laneB + p * 4352 + ks * 32);
            mma16816(acc[2 * p],     ah, bh[0], bh[1]);
            mma16816(acc[2 * p + 1], ah, bh[2], bh[3]);
        }
    }

    // epilogue 2: z + bias, BN partial sums
#pragma unroll
    for (int nt = 0; nt < 8; nt++) {
        int c0 = wc * 64 + nt * 8 + qcol * 2;
        float b0v = bblk[c0], b1v = bblk[c0 + 1];
        float z00 = acc[nt][0] + b0v, z01 = acc[nt][1] + b1v;
        float z10 = acc[nt][2] + b0v, z11 = acc[nt][3] + b1v;
        *(uint32_t*)(d_z + (size_t)(row0 + r0) * HID + c0)     = packh(z00, z01);
        *(uint32_t*)(d_z + (size_t)(row0 + r0 + 8) * HID + c0) = packh(z10, z11);
        float s0 = z00 + z10, s1 = z01 + z11;
        float q0 = z00 * z00 + z10 * z10, q1 = z01 * z01 + z11 * z11;
#pragma unroll
        for (int off = 4; off <= 16; off <<= 1) {
            s0 += __shfl_xor_sync(0xffffffffu, s0, off);
            s1 += __shfl_xor_sync(0xffffffffu, s1, off);
            q0 += __shfl_xor_sync(0xffffffffu, q0, off);
            q1 += __shfl_xor_sync(0xffffffffu, q1, off);
        }
        if (lane < 4) {
            wS[wr * 128 + c0] = s0; wS[wr * 128 + c0 + 1] = s1;
            wQ[wr * 128 + c0] = q0; wQ[wr * 128 + c0 + 1] = q1;
        }
    }
    __syncthreads();
    if (tid < 128) {
        float s = 0.f, q = 0.f;
#pragma unroll
        for (int g = 0; g < 8; g++) { s += wS[g * 128 + tid]; q += wQ[g * 128 + tid]; }
        d_colpart[blockIdx.x * 256 + tid] = s;
        d_colpart[blockIdx.x * 256 + 128 + tid] = q;
        d_mask[row0 + tid] = rowsq[tid];
    }
}

// ============================================================================
// kB: finalize BN stats -> scale/shift
// ============================================================================
__global__ void kB(const float* __restrict__ gamma, const float* __restrict__ beta) {
    __shared__ float rs[256], rq[256];
    int c = blockIdx.x;
    int tid = threadIdx.x;
    float s = 0.f, q = 0.f;
    for (int i = tid; i < NBLK_A; i += 256) {
        s += d_colpart[i * 256 + c];
        q += d_colpart[i * 256 + 128 + c];
    }
    rs[tid] = s; rq[tid] = q;
    __syncthreads();
    for (int st = 128; st > 0; st >>= 1) {
        if (tid < st) { rs[tid] += rs[tid + st]; rq[tid] += rq[tid + st]; }
        __syncthreads();
    }
    if (tid == 0) {
        float mu  = rs[0] * (1.f / (float)NROWS);
        float var = rq[0] * (1.f / (float)NROWS) - mu * mu;
        float sc  = gamma[c] * rsqrtf(var + 1e-5f);
        d_ss[c]       = sc;
        d_ss[128 + c] = beta[c] - mu * sc;
    }
}

// ============================================================================
// kC_mma: h2 = relu(bn(z)) + h; t = (h2@Wfc + b)*mask + gumbel
// FUSED: per-block softmax stats (max + sumexp per h over the 128 rows)
// emitted directly from register outputs — replaces kD1 entirely.
// ============================================================================
__global__ __launch_bounds__(256, 2) void kC_mma(
    const float* __restrict__ gumbel, const float* __restrict__ Wfc,
    const float* __restrict__ bfc)
{
    extern __shared__ char smem[];
    const uint32_t sb = smem_u32(smem);
    const int tid = threadIdx.x;
    const int lane = tid & 31;
    const int w = tid >> 5;
    const int row0 = blockIdx.x * 128;

    float* scs  = (float*)(smem + KC_SC);
    float* shs  = (float*)(smem + KC_SH);
    float* bfcs = (float*)(smem + KC_BFC);
    float* stm  = (float*)(smem + KC_STM);   // [warp][h] max
    float* sts  = (float*)(smem + KC_STS);   // [warp][h] sumexp
    float* Mb   = (float*)(smem + KC_MB);    // [h] block max

#pragma unroll
    for (int u = 0; u < 4; u++) {
        int e = tid + u * 256;
        int k = e >> 3, j = e & 7;
        *(__half*)(smem + KC_WF + (j * 136 + k) * 2) = __float2half_rn(Wfc[e]);
    }
    if (tid < 128) { scs[tid] = d_ss[tid]; shs[tid] = d_ss[128 + tid]; }
    if (tid < 8)   bfcs[tid] = bfc[tid];
    __syncthreads();

    char* ah = smem + w * 4352;
    {
        const int c = lane * 4;
        float4 sc4 = *(float4*)(scs + c);
        float4 sh4 = *(float4*)(shs + c);
#pragma unroll
        for (int i = 0; i < 16; i++) {
            size_t g = (size_t)(row0 + w * 16 + i) * HID + c;
            uint2 zp = *(const uint2*)(d_z + g);
            uint2 hp = *(const uint2*)(d_h + g);
            float2 z0 = __half22float2(*(__half2*)&zp.x);
            float2 z1 = __half22float2(*(__half2*)&zp.y);
            float2 hh0 = __half22float2(*(__half2*)&hp.x);
            float2 hh1 = __half22float2(*(__half2*)&hp.y);
            float t0 = fmaxf(z0.x * sc4.x + sh4.x, 0.f) + hh0.x;
            float t1 = fmaxf(z0.y * sc4.y + sh4.y, 0.f) + hh0.y;
            float t2 = fmaxf(z1.x * sc4.z + sh4.z, 0.f) + hh1.x;
            float t3 = fmaxf(z1.y * sc4.w + sh4.w, 0.f) + hh1.y;
            *(uint2*)(ah + (i * 136 + c) * 2) =
                make_uint2(packh(t0, t1), packh(t2, t3));
        }
    }
    __syncwarp();

    float acc[4] = {0.f, 0.f, 0.f, 0.f};
    const uint32_t aB = sb + w * 4352 +
        (uint32_t)(((lane & 15) * 136 + ((lane >> 4) << 3)) * 2);
    const uint32_t bB = sb + KC_WF +
        (uint32_t)(((lane & 7) * 136 + ((lane >> 3) & 1) * 8) * 2);
#pragma unroll
    for (int ks = 0; ks < 8; ks++) {
        uint32_t ahf[4];
        ldsm4(ahf, aB + ks * 32);
        uint32_t bh0, bh1;
        ldsm2(bh0, bh1, bB + ks * 32);
        mma16816(acc, ahf, bh0, bh1);
    }

    const int qrow = lane >> 2, qcol = lane & 3;
    const int r0 = row0 + w * 16 + qrow;
    float m0v = d_mask[r0], m1v = d_mask[r0 + 8];
    float b0 = bfcs[qcol * 2], b1 = bfcs[qcol * 2 + 1];
    float2 g0 = *(const float2*)(gumbel + (size_t)r0 * 8 + qcol * 2);
    float2 g1 = *(const float2*)(gumbel + (size_t)(r0 + 8) * 8 + qcol * 2);
    float t00 = (acc[0] + b0) * m0v + g0.x;
    float t01 = (acc[1] + b1) * m0v + g0.y;
    float t10 = (acc[2] + b0) * m1v + g1.x;
    float t11 = (acc[3] + b1) * m1v + g1.y;
    *(float2*)(d_t + (size_t)r0 * 8 + qcol * 2)       = make_float2(t00, t01);
    *(float2*)(d_t + (size_t)(r0 + 8) * 8 + qcol * 2) = make_float2(t10, t11);

    // ---- fused softmax stats over this block's 128 rows ----
    // lane = qrow*4 + qcol: butterfly over qrow (offsets 4/8/16) keeps qcol.
    float mx0 = fmaxf(t00, t10), mx1 = fmaxf(t01, t11);
#pragma unroll
    for (int off = 4; off <= 16; off <<= 1) {
        mx0 = fmaxf(mx0, __shfl_xor_sync(0xffffffffu, mx0, off));
        mx1 = fmaxf(mx1, __shfl_xor_sync(0xffffffffu, mx1, off));
    }
    if (lane < 4) { stm[w * 8 + qcol * 2] = mx0; stm[w * 8 + qcol * 2 + 1] = mx1; }
    __syncthreads();
    if (tid < 8) {
        float M = stm[tid];
#pragma unroll
        for (int ww = 1; ww < 8; ww++) M = fmaxf(M, stm[ww * 8 + tid]);
        Mb[tid] = M;
    }
    __syncthreads();
    float M0 = Mb[qcol * 2], M1 = Mb[qcol * 2 + 1];
    float se0 = expf(t00 - M0) + expf(t10 - M0);
    float se1 = expf(t01 - M1) + expf(t11 - M1);
#pragma unroll
    for (int off = 4; off <= 16; off <<= 1) {
        se0 += __shfl_xor_sync(0xffffffffu, se0, off);
        se1 += __shfl_xor_sync(0xffffffffu, se1, off);
    }
    if (lane < 4) { sts[w * 8 + qcol * 2] = se0; sts[w * 8 + qcol * 2 + 1] = se1; }
    __syncthreads();
    if (tid < 8) {
        float S = 0.f;
#pragma unroll
        for (int ww = 0; ww < 8; ww++) S += sts[ww * 8 + tid];
        d_cmax[blockIdx.x * HH + tid] = Mb[tid];
        d_csum[blockIdx.x * HH + tid] = S;
    }
}

// ============================================================================
// kD2: combine 32 chunk stats per b -> global M, invS per (b,h)
// ============================================================================
__global__ void kD2() {
    int b = blockIdx.x, h = threadIdx.x;
    if (h >= 8) return;
    float M = -1e30f;
#pragma unroll
    for (int ch = 0; ch < 32; ch++)
        M = fmaxf(M, d_cmax[(b * 32 + ch) * HH + h]);
    float S = 0.f;
#pragma unroll
    for (int ch = 0; ch < 32; ch++)
        S += d_csum[(b * 32 + ch) * HH + h] * expf(d_cmax[(b * 32 + ch) * HH + h] - M);
    d_M[b * HH + h] = M;
    d_invS[b * HH + h] = 1.f / S;
}

// ============================================================================
// kE: pooled partials with fused softmax normalization
// ============================================================================
__global__ __launch_bounds__(256) void kE(const float* __restrict__ x) {
    __shared__ float wsm[64 * 8];
    __shared__ float Ms[8], iSs[8];
    int b = blockIdx.x >> 4, oc = blockIdx.x & 15;
    int tid = threadIdx.x;
    int fq = tid & 63;
    int og = tid >> 6;
    if (tid < 8)  Ms[tid] = d_M[b * HH + tid];
    if (tid >= 8 && tid < 16) iSs[tid - 8] = d_invS[b * HH + tid - 8];
    float acc[8][4];
#pragma unroll
    for (int h = 0; h < 8; h++)
#pragma unroll
        for (int j = 0; j < 4; j++) acc[h][j] = 0.f;
    int o0 = oc * 256;
    __syncthreads();

    for (int chunk = 0; chunk < 256; chunk += 64) {
        size_t wbase = ((size_t)b * OO + o0 + chunk) * 8;
        {
            int h0 = (tid * 2) & 7;
            float2 tv = *(const float2*)(d_t + wbase + tid * 2);
            wsm[tid * 2]     = expf(tv.x - Ms[h0])     * iSs[h0];
            wsm[tid * 2 + 1] = expf(tv.y - Ms[h0 + 1]) * iSs[h0 + 1];
        }
        __syncthreads();
#pragma unroll 4
        for (int t = 0; t < 16; t++) {
            int oo = og * 16 + t;
            float4 xv = *(const float4*)(x + ((size_t)b * OO + o0 + chunk + oo) * FF + fq * 4);
#pragma unroll
            for (int h = 0; h < 8; h++) {
                float wv = wsm[oo * 8 + h];
                acc[h][0] += wv * xv.x; acc[h][1] += wv * xv.y;
                acc[h][2] += wv * xv.z; acc[h][3] += wv * xv.w;
            }
        }
        __syncthreads();
    }
#pragma unroll
    for (int h = 0; h < 8; h++)
        *(float4*)(d_partial + (((size_t)b * 64 + oc * 4 + og) * 8 + h) * FF + fq * 4) =
            make_float4(acc[h][0], acc[h][1], acc[h][2], acc[h][3]);
}

// ============================================================================
// kF: final reduce over 64 partials
// ============================================================================
__global__ __launch_bounds__(256) void kF(float* __restrict__ out) {
    int bh = blockIdx.x;
    int b = bh >> 3, h = bh & 7;
    int f = threadIdx.x;
    float s = 0.f;
#pragma unroll
    for (int p = 0; p < 64; p++)
        s += d_partial[(((size_t)b * 64 + p) * 8 + h) * FF + f];
    out[(size_t)bh * FF + f] = s;
}

// ============================================================================
extern "C" void kernel_launch(void* const* d_in, const int* in_sizes, int n_in,
                              void* d_out, int out_size) {
    const float* x      = (const float*)d_in[0];
    const float* gumbel = (const float*)d_in[1];
    const float* Win    = (const float*)d_in[2];
    const float* bin    = (const float*)d_in[3];
    const float* Wblk   = (const float*)d_in[4];
    const float* bblk   = (const float*)d_in[5];
    const float* gamma  = (const float*)d_in[6];
    const float* beta   = (const float*)d_in[7];
    const float* Wfc    = (const float*)d_in[8];
    const float* bfc    = (const float*)d_in[9];
    float* out = (float*)d_out;

    cudaFuncSetAttribute(kA_mma, cudaFuncAttributeMaxDynamicSharedMemorySize, SMEM_TOTAL);
    cudaFuncSetAttribute(kC_mma, cudaFuncAttributeMaxDynamicSharedMemorySize, KC_SMEM);

    kW<<<128, 256>>>(Win, Wblk);
    kA_mma<<<NBLK_A, 512, SMEM_TOTAL>>>(x, bin, bblk);
    kB<<<128, 256>>>(gamma, beta);
    kC_mma<<<NROWS / 128, 256, KC_SMEM>>>(gumbel, Wfc, bfc);
    kD2<<<BB, 8>>>();
    kE<<<BB * 16, 256>>>(x);
    kF<<<BB * HH, 256>>>(out);
}

// round 16
// speedup vs baseline: 1.1356x; 1.0110x over previous
#include <cuda_runtime.h>
#include <cuda_fp16.h>
#include <cstdint>

#define NROWS 131072
#define BB 32
#define OO 4096
#define FF 256
#define HH 8
#define HID 128
#define NBLK_A 1024   // NROWS / 128

// ---------------- scratch (device globals) ----------------
__device__ __half d_h[NROWS * HID];
__device__ __half d_z[NROWS * HID];
__device__ float d_mask[NROWS];
__device__ float d_colpart[NBLK_A * 256];
__device__ float d_ss[256];
__device__ float d_t[NROWS * HH];
__device__ float d_cmax[1024 * HH];
__device__ float d_csum[1024 * HH];
__device__ float d_M[BB * HH];
__device__ float d_invS[BB * HH];
__device__ float d_partial[BB * 64 * HH * FF];
__device__ __half d_WinT[HID * FF];
__device__ __half d_WblkT[HID * HID];

// ---------------- smem layout for kA (bytes) ----------------
#define TILE_BYTES 34816           // 128 * 272
#define AS    0
#define BS0   34816
#define BS1   69632
#define BS2   104448
#define ROWSQ 139264               // 128 floats
#define WSUM  139776               // 8*128 floats
#define WSQ   143872               // 8*128 floats
#define SMEM_TOTAL 147968          // 1 CTA/SM

// ---------------- smem layout for kC (bytes) ----------------
#define KC_WF   34816              // 8 x 136 fp16
#define KC_SC   36992
#define KC_SH   37504
#define KC_BFC  38016
#define KC_STM  38048
#define KC_STS  38304
#define KC_MB   38560
#define KC_SMEM 38592

// ---------------- helpers ----------------
__device__ __forceinline__ uint32_t smem_u32(const void* p) {
    uint32_t a;
    asm("{ .reg .u64 t; cvta.to.shared.u64 t, %1; cvt.u32.u64 %0, t; }" : "=r"(a) : "l"(p));
    return a;
}
__device__ __forceinline__ void ldsm4(uint32_t* r, uint32_t addr) {
    asm volatile("ldmatrix.sync.aligned.m8n8.x4.shared.b16 {%0,%1,%2,%3}, [%4];"
        : "=r"(r[0]), "=r"(r[1]), "=r"(r[2]), "=r"(r[3]) : "r"(addr));
}
__device__ __forceinline__ void ldsm2(uint32_t& r0, uint32_t& r1, uint32_t addr) {
    asm volatile("ldmatrix.sync.aligned.m8n8.x2.shared.b16 {%0,%1}, [%2];"
        : "=r"(r0), "=r"(r1) : "r"(addr));
}
__device__ __forceinline__ void mma16816(float* c, const uint32_t* a, uint32_t b0, uint32_t b1) {
    asm volatile("mma.sync.aligned.m16n8k16.row.col.f32.f16.f16.f32 "
        "{%0,%1,%2,%3}, {%4,%5,%6,%7}, {%8,%9}, {%0,%1,%2,%3};"
        : "+f"(c[0]), "+f"(c[1]), "+f"(c[2]), "+f"(c[3])
        : "r"(a[0]), "r"(a[1]), "r"(a[2]), "r"(a[3]), "r"(b0), "r"(b1));
}
__device__ __forceinline__ uint32_t packh(float a, float b) {
    __half2 hp = __floats2half2_rn(a, b);
    return *reinterpret_cast<uint32_t*>(&hp);
}

// ============================================================================
// kW: convert weights to fp16, transposed to [N][K]
// ============================================================================
__global__ void kW(const float* __restrict__ Win, const float* __restrict__ Wblk) {
    int e = blockIdx.x * 256 + threadIdx.x;
    if (e < HID * FF) {
        int n = e >> 8, k = e & 255;
        d_WinT[e] = __float2half_rn(Win[(size_t)k * HID + n]);
    }
    if (e < HID * HID) {
        int n = e >> 7, k = e & 127;
        d_WblkT[e] = __float2half_rn(Wblk[(size_t)k * HID + n]);
    }
}

// ============================================================================
// kA_mma: h = relu(x@Win+b); z = h@Wblk+b; BN col partials; row mask
// Round-14 base + x chunk-1 REGISTER PREFETCH: the 8xfloat4 LDGs for chunk 1
// are issued before MMA chunk 0, so the DRAM round trip hides under ~2us of
// LDSM+HMMA issue. Pack/STS happen after the existing drain barrier.
// ============================================================================
__global__ __launch_bounds__(512, 1) void kA_mma(
    const float* __restrict__ x, const float* __restrict__ bin,
    const float* __restrict__ bblk)
{
    extern __shared__ char smem[];
    const uint32_t sb = smem_u32(smem);
    const int tid = threadIdx.x;
    const int lane = tid & 31;
    const int w = tid >> 5;
    const int wr = w >> 1;
    const int wc = w & 1;
    const int row0 = blockIdx.x * 128;

    float* rowsq = (float*)(smem + ROWSQ);
    float* wS = (float*)(smem + WSUM);
    float* wQ = (float*)(smem + WSQ);
    if (tid < 128) rowsq[tid] = 0.f;

    // persistent B preload: WinT k0, WinT k1, WblkT (L2-hot)
#pragma unroll
    for (int i = 0; i < 4; i++) {
        int idx = tid + i * 512;
        int n = idx >> 4, q = idx & 15;
        uint32_t doff = (uint32_t)(n * 272 + q * 16);
        *(uint4*)(smem + BS0 + doff) = *(const uint4*)(d_WinT + (size_t)n * FF + q * 8);
        *(uint4*)(smem + BS1 + doff) = *(const uint4*)(d_WinT + (size_t)n * FF + 128 + q * 8);
        *(uint4*)(smem + BS2 + doff) = *(const uint4*)(d_WblkT + (size_t)n * HID + q * 8);
    }

    float acc[8][4];
#pragma unroll
    for (int nt = 0; nt < 8; nt++)
#pragma unroll
        for (int j = 0; j < 4; j++) acc[nt][j] = 0.f;

    const uint32_t aBase = sb + AS +
        (uint32_t)((wr * 16 + (lane & 15)) * 272 + ((lane >> 4) << 3) * 2);
    const uint32_t laneB = (uint32_t)(wc * 64 * 272 +
        ((lane & 7) + ((lane >> 4) << 3)) * 272 + ((lane >> 3) & 1) * 16);

    // x chunk 0 -> fp16 A + row-nonzero vote
#pragma unroll
    for (int i = 0; i < 8; i++) {
        int idx = tid + i * 512;
        int r = idx >> 5, c4 = idx & 31;
        float4 v = *(const float4*)(x + (size_t)(row0 + r) * FF + c4 * 4);
        int nz = (v.x != 0.f) | (v.y != 0.f) | (v.z != 0.f) | (v.w != 0.f);
        if (__any_sync(0xffffffffu, nz) && lane == 0) rowsq[r] = 1.f;
        *(uint2*)(smem + AS + (uint32_t)(r * 272 + c4 * 8)) =
            make_uint2(packh(v.x, v.y), packh(v.z, v.w));
    }
    __syncthreads();

    // PREFETCH: issue x chunk-1 LDGs now; they complete under MMA chunk 0.
    float4 px[8];
#pragma unroll
    for (int i = 0; i < 8; i++) {
        int idx = tid + i * 512;
        int r = idx >> 5, c4 = idx & 31;
        px[i] = *(const float4*)(x + (size_t)(row0 + r) * FF + 128 + c4 * 4);
    }

    // MMA chunk 0 (B = BS0)
#pragma unroll
    for (int ks = 0; ks < 8; ks++) {
        uint32_t ah[4];
        ldsm4(ah, aBase + ks * 32);
#pragma unroll
        for (int p = 0; p < 4; p++) {
            uint32_t bh[4];
            ldsm4(bh, sb + BS0 + laneB + p * 4352 + ks * 32);
            mma16816(acc[2 * p],     ah, bh[0], bh[1]);
            mma16816(acc[2 * p + 1], ah, bh[2], bh[3]);
        }
    }
    __syncthreads();   // drain chunk-0 A reads

    // x chunk 1: vote + pack from prefetched registers -> A
#pragma unroll
    for (int i = 0; i < 8; i++) {
        int idx = tid + i * 512;
        int r = idx >> 5, c4 = idx & 31;
        float4 v = px[i];
        int nz = (v.x != 0.f) | (v.y != 0.f) | (v.z != 0.f) | (v.w != 0.f);
        if (__any_sync(0xffffffffu, nz) && lane == 0) rowsq[r] = 1.f;
        *(uint2*)(smem + AS + (uint32_t)(r * 272 + c4 * 8)) =
            make_uint2(packh(v.x, v.y), packh(v.z, v.w));
    }
    __syncthreads();

    // MMA chunk 1 (B = BS1)
#pragma unroll
    for (int ks = 0; ks < 8; ks++) {
        uint32_t ah[4];
        ldsm4(ah, aBase + ks * 32);
#pragma unroll
        for (int p = 0; p < 4; p++) {
            uint32_t bh[4];
            ldsm4(bh, sb + BS1 + laneB + p * 4352 + ks * 32);
            mma16816(acc[2 * p],     ah, bh[0], bh[1]);
            mma16816(acc[2 * p + 1], ah, bh[2], bh[3]);
        }
    }
    // RACE FIX: drain all GEMM1 A reads before overwriting rows with h
    __syncthreads();

    // epilogue 1: h = relu(acc + bin)
    const int qrow = lane >> 2, qcol = lane & 3;
    const int r0 = wr * 16 + qrow;
#pragma unroll
    for (int nt = 0; nt < 8; nt++) {
        int c0 = wc * 64 + nt * 8 + qcol * 2;
        float b0v = bin[c0], b1v = bin[c0 + 1];
        float h00 = fmaxf(acc[nt][0] + b0v, 0.f);
        float h01 = fmaxf(acc[nt][1] + b1v, 0.f);
        float h10 = fmaxf(acc[nt][2] + b0v, 0.f);
        float h11 = fmaxf(acc[nt][3] + b1v, 0.f);
        uint32_t p00 = packh(h00, h01);
        uint32_t p10 = packh(h10, h11);
        *(uint32_t*)(d_h + (size_t)(row0 + r0) * HID + c0)     = p00;
        *(uint32_t*)(d_h + (size_t)(row0 + r0 + 8) * HID + c0) = p10;
        *(uint32_t*)(smem + AS + (r0 * 136 + c0) * 2)       = p00;
        *(uint32_t*)(smem + AS + ((r0 + 8) * 136 + c0) * 2) = p10;
        acc[nt][0] = acc[nt][1] = acc[nt][2] = acc[nt][3] = 0.f;
    }
    __syncthreads();

    // GEMM2: z = h @ Wblk (B = BS2, resident)
#pragma unroll
    for (int ks = 0; ks < 8; ks++) {
        uint32_t ah[4];
        ldsm4(ah, aBase + ks * 32);
#pragma unroll
        for (int p = 0; p < 4; p++) {
            uint32_t bh[4];
            ldsm4(bh, sb + BS2 + laneB + p * 4352 + ks * 32);
            mma16816(acc[2 * p],     ah, bh[0], bh[1]);
            mma16816(acc[2 * p + 1], ah, bh[2], bh[3]);
        }
    }

    // epilogue 2: z + bias, BN partial sums
#pragma unroll
    for (int nt = 0; nt < 8; nt++) {
        int c0 = wc * 64 + nt * 8 + qcol * 2;
        float b0v = bblk[c0], b1v = bblk[c0 + 1];
        float z00 = acc[nt][0] + b0v, z01 = acc[nt][1] + b1v;
        float z10 = acc[nt][2] + b0v, z11 = acc[nt][3] + b1v;
        *(uint32_t*)(d_z + (size_t)(row0 + r0) * HID + c0)     = packh(z00, z01);
        *(uint32_t*)(d_z + (size_t)(row0 + r0 + 8) * HID + c0) = packh(z10, z11);
        float s0 = z00 + z10, s1 = z01 + z11;
        float q0 = z00 * z00 + z10 * z10, q1 = z01 * z01 + z11 * z11;
#pragma unroll
        for (int off = 4; off <= 16; off <<= 1) {
            s0 += __shfl_xor_sync(0xffffffffu, s0, off);
            s1 += __shfl_xor_sync(0xffffffffu, s1, off);
            q0 += __shfl_xor_sync(0xffffffffu, q0, off);
            q1 += __shfl_xor_sync(0xffffffffu, q1, off);
        }
        if (lane < 4) {
            wS[wr * 128 + c0] = s0; wS[wr * 128 + c0 + 1] = s1;
            wQ[wr * 128 + c0] = q0; wQ[wr * 128 + c0 + 1] = q1;
        }
    }
    __syncthreads();
    if (tid < 128) {
        float s = 0.f, q = 0.f;
#pragma unroll
        for (int g = 0; g < 8; g++) { s += wS[g * 128 + tid]; q += wQ[g * 128 + tid]; }
        d_colpart[blockIdx.x * 256 + tid] = s;
        d_colpart[blockIdx.x * 256 + 128 + tid] = q;
        d_mask[row0 + tid] = rowsq[tid];
    }
}

// ============================================================================
// kB: finalize BN stats -> scale/shift
// ============================================================================
__global__ void kB(const float* __restrict__ gamma, const float* __restrict__ beta) {
    __shared__ float rs[256], rq[256];
    int c = blockIdx.x;
    int tid = threadIdx.x;
    float s = 0.f, q = 0.f;
    for (int i = tid; i < NBLK_A; i += 256) {
        s += d_colpart[i * 256 + c];
        q += d_colpart[i * 256 + 128 + c];
    }
    rs[tid] = s; rq[tid] = q;
    __syncthreads();
    for (int st = 128; st > 0; st >>= 1) {
        if (tid < st) { rs[tid] += rs[tid + st]; rq[tid] += rq[tid + st]; }
        __syncthreads();
    }
    if (tid == 0) {
        float mu  = rs[0] * (1.f / (float)NROWS);
        float var = rq[0] * (1.f / (float)NROWS) - mu * mu;
        float sc  = gamma[c] * rsqrtf(var + 1e-5f);
        d_ss[c]       = sc;
        d_ss[128 + c] = beta[c] - mu * sc;
    }
}

// ============================================================================
// kC_mma: h2 = relu(bn(z)) + h; t = (h2@Wfc + b)*mask + gumbel
// + fused per-block softmax stats (replaces kD1)
// ============================================================================
__global__ __launch_bounds__(256, 2) void kC_mma(
    const float* __restrict__ gumbel, const float* __restrict__ Wfc,
    const float* __restrict__ bfc)
{
    extern __shared__ char smem[];
    const uint32_t sb = smem_u32(smem);
    const int tid = threadIdx.x;
    const int lane = tid & 31;
    const int w = tid >> 5;
    const int row0 = blockIdx.x * 128;

    float* scs  = (float*)(smem + KC_SC);
    float* shs  = (float*)(smem + KC_SH);
    float* bfcs = (float*)(smem + KC_BFC);
    float* stm  = (float*)(smem + KC_STM);
    float* sts  = (float*)(smem + KC_STS);
    float* Mb   = (float*)(smem + KC_MB);

#pragma unroll
    for (int u = 0; u < 4; u++) {
        int e = tid + u * 256;
        int k = e >> 3, j = e & 7;
        *(__half*)(smem + KC_WF + (j * 136 + k) * 2) = __float2half_rn(Wfc[e]);
    }
    if (tid < 128) { scs[tid] = d_ss[tid]; shs[tid] = d_ss[128 + tid]; }
    if (tid < 8)   bfcs[tid] = bfc[tid];
    __syncthreads();

    char* ah = smem + w * 4352;
    {
        const int c = lane * 4;
        float4 sc4 = *(float4*)(scs + c);
        float4 sh4 = *(float4*)(shs + c);
#pragma unroll
        for (int i = 0; i < 16; i++) {
            size_t g = (size_t)(row0 + w * 16 + i) * HID + c;
            uint2 zp = *(const uint2*)(d_z + g);
            uint2 hp = *(const uint2*)(d_h + g);
            float2 z0 = __half22float2(*(__half2*)&zp.x);
            float2 z1 = __half22float2(*(__half2*)&zp.y);
            float2 hh0 = __half22float2(*(__half2*)&hp.x);
            float2 hh1 = __half22float2(*(__half2*)&hp.y);
            float t0 = fmaxf(z0.x * sc4.x + sh4.x, 0.f) + hh0.x;
            float t1 = fmaxf(z0.y * sc4.y + sh4.y, 0.f) + hh0.y;
            float t2 = fmaxf(z1.x * sc4.z + sh4.z, 0.f) + hh1.x;
            float t3 = fmaxf(z1.y * sc4.w + sh4.w, 0.f) + hh1.y;
            *(uint2*)(ah + (i * 136 + c) * 2) =
                make_uint2(packh(t0, t1), packh(t2, t3));
        }
    }
    __syncwarp();

    float acc[4] = {0.f, 0.f, 0.f, 0.f};
    const uint32_t aB = sb + w * 4352 +
        (uint32_t)(((lane & 15) * 136 + ((lane >> 4) << 3)) * 2);
    const uint32_t bB = sb + KC_WF +
        (uint32_t)(((lane & 7) * 136 + ((lane >> 3) & 1) * 8) * 2);
#pragma unroll
    for (int ks = 0; ks < 8; ks++) {
        uint32_t ahf[4];
        ldsm4(ahf, aB + ks * 32);
        uint32_t bh0, bh1;
        ldsm2(bh0, bh1, bB + ks * 32);
        mma16816(acc, ahf, bh0, bh1);
    }

    const int qrow = lane >> 2, qcol = lane & 3;
    const int r0 = row0 + w * 16 + qrow;
    float m0v = d_mask[r0], m1v = d_mask[r0 + 8];
    float b0 = bfcs[qcol * 2], b1 = bfcs[qcol * 2 + 1];
    float2 g0 = *(const float2*)(gumbel + (size_t)r0 * 8 + qcol * 2);
    float2 g1 = *(const float2*)(gumbel + (size_t)(r0 + 8) * 8 + qcol * 2);
    float t00 = (acc[0] + b0) * m0v + g0.x;
    float t01 = (acc[1] + b1) * m0v + g0.y;
    float t10 = (acc[2] + b0) * m1v + g1.x;
    float t11 = (acc[3] + b1) * m1v + g1.y;
    *(float2*)(d_t + (size_t)r0 * 8 + qcol * 2)       = make_float2(t00, t01);
    *(float2*)(d_t + (size_t)(r0 + 8) * 8 + qcol * 2) = make_float2(t10, t11);

    // fused softmax stats over this block's 128 rows
    float mx0 = fmaxf(t00, t10), mx1 = fmaxf(t01, t11);
#pragma unroll
    for (int off = 4; off <= 16; off <<= 1) {
        mx0 = fmaxf(mx0, __shfl_xor_sync(0xffffffffu, mx0, off));
        mx1 = fmaxf(mx1, __shfl_xor_sync(0xffffffffu, mx1, off));
    }
    if (lane < 4) { stm[w * 8 + qcol * 2] = mx0; stm[w * 8 + qcol * 2 + 1] = mx1; }
    __syncthreads();
    if (tid < 8) {
        float M = stm[tid];
#pragma unroll
        for (int ww = 1; ww < 8; ww++) M = fmaxf(M, stm[ww * 8 + tid]);
        Mb[tid] = M;
    }
    __syncthreads();
    float M0 = Mb[qcol * 2], M1 = Mb[qcol * 2 + 1];
    float se0 = expf(t00 - M0) + expf(t10 - M0);
    float se1 = expf(t01 - M1) + expf(t11 - M1);
#pragma unroll
    for (int off = 4; off <= 16; off <<= 1) {
        se0 += __shfl_xor_sync(0xffffffffu, se0, off);
        se1 += __shfl_xor_sync(0xffffffffu, se1, off);
    }
    if (lane < 4) { sts[w * 8 + qcol * 2] = se0; sts[w * 8 + qcol * 2 + 1] = se1; }
    __syncthreads();
    if (tid < 8) {
        float S = 0.f;
#pragma unroll
        for (int ww = 0; ww < 8; ww++) S += sts[ww * 8 + tid];
        d_cmax[blockIdx.x * HH + tid] = Mb[tid];
        d_csum[blockIdx.x * HH + tid] = S;
    }
}

// ============================================================================
// kD2: combine 32 chunk stats per b -> global M, invS per (b,h)
// ============================================================================
__global__ void kD2() {
    int b = blockIdx.x, h = threadIdx.x;
    if (h >= 8) return;
    float M = -1e30f;
#pragma unroll
    for (int ch = 0; ch < 32; ch++)
        M = fmaxf(M, d_cmax[(b * 32 + ch) * HH + h]);
    float S = 0.f;
#pragma unroll
    for (int ch = 0; ch < 32; ch++)
        S += d_csum[(b * 32 + ch) * HH + h] * expf(d_cmax[(b * 32 + ch) * HH + h] - M);
    d_M[b * HH + h] = M;
    d_invS[b * HH + h] = 1.f / S;
}

// ============================================================================
// kE: pooled partials with fused softmax normalization
// ============================================================================
__global__ __launch_bounds__(256) void kE(const float* __restrict__ x) {
    __shared__ float wsm[64 * 8];
    __shared__ float Ms[8], iSs[8];
    int b = blockIdx.x >> 4, oc = blockIdx.x & 15;
    int tid = threadIdx.x;
    int fq = tid & 63;
    int og = tid >> 6;
    if (tid < 8)  Ms[tid] = d_M[b * HH + tid];
    if (tid >= 8 && tid < 16) iSs[tid - 8] = d_invS[b * HH + tid - 8];
    float acc[8][4];
#pragma unroll
    for (int h = 0; h < 8; h++)
#pragma unroll
        for (int j = 0; j < 4; j++) acc[h][j] = 0.f;
    int o0 = oc * 256;
    __syncthreads();

    for (int chunk = 0; chunk < 256; chunk += 64) {
        size_t wbase = ((size_t)b * OO + o0 + chunk) * 8;
        {
            int h0 = (tid * 2) & 7;
            float2 tv = *(const float2*)(d_t + wbase + tid * 2);
            wsm[tid * 2]     = expf(tv.x - Ms[h0])     * iSs[h0];
            wsm[tid * 2 + 1] = expf(tv.y - Ms[h0 + 1]) * iSs[h0 + 1];
        }
        __syncthreads();
#pragma unroll 4
        for (int t = 0; t < 16; t++) {
            int oo = og * 16 + t;
            float4 xv = *(const float4*)(x + ((size_t)b * OO + o0 + chunk + oo) * FF + fq * 4);
#pragma unroll
            for (int h = 0; h < 8; h++) {
                float wv = wsm[oo * 8 + h];
                acc[h][0] += wv * xv.x; acc[h][1] += wv * xv.y;
                acc[h][2] += wv * xv.z; acc[h][3] += wv * xv.w;
            }
        }
        __syncthreads();
    }
#pragma unroll
    for (int h = 0; h < 8; h++)
        *(float4*)(d_partial + (((size_t)b * 64 + oc * 4 + og) * 8 + h) * FF + fq * 4) =
            make_float4(acc[h][0], acc[h][1], acc[h][2], acc[h][3]);
}

// ============================================================================
// kF: final reduce over 64 partials
// ============================================================================
__global__ __launch_bounds__(256) void kF(float* __restrict__ out) {
    int bh = blockIdx.x;
    int b = bh >> 3, h = bh & 7;
    int f = threadIdx.x;
    float s = 0.f;
#pragma unroll
    for (int p = 0; p < 64; p++)
        s += d_partial[(((size_t)b * 64 + p) * 8 + h) * FF + f];
    out[(size_t)bh * FF + f] = s;
}

// ============================================================================
extern "C" void kernel_launch(void* const* d_in, const int* in_sizes, int n_in,
                              void* d_out, int out_size) {
    const float* x      = (const float*)d_in[0];
    const float* gumbel = (const float*)d_in[1];
    const float* Win    = (const float*)d_in[2];
    const float* bin    = (const float*)d_in[3];
    const float* Wblk   = (const float*)d_in[4];
    const float* bblk   = (const float*)d_in[5];
    const float* gamma  = (const float*)d_in[6];
    const float* beta   = (const float*)d_in[7];
    const float* Wfc    = (const float*)d_in[8];
    const float* bfc    = (const float*)d_in[9];
    float* out = (float*)d_out;

    cudaFuncSetAttribute(kA_mma, cudaFuncAttributeMaxDynamicSharedMemorySize, SMEM_TOTAL);
    cudaFuncSetAttribute(kC_mma, cudaFuncAttributeMaxDynamicSharedMemorySize, KC_SMEM);

    kW<<<128, 256>>>(Win, Wblk);
    kA_mma<<<NBLK_A, 512, SMEM_TOTAL>>>(x, bin, bblk);
    kB<<<128, 256>>>(gamma, beta);
    kC_mma<<<NROWS / 128, 256, KC_SMEM>>>(gumbel, Wfc, bfc);
    kD2<<<BB, 8>>>();
    kE<<<BB * 16, 256>>>(x);
    kF<<<BB * HH, 256>>>(out);
}

// round 17
// speedup vs baseline: 1.2175x; 1.0721x over previous
#include <cuda_runtime.h>
#include <cuda_fp16.h>
#include <cstdint>

#define NROWS 131072
#define BB 32
#define OO 4096
#define FF 256
#define HH 8
#define HID 128
#define NBLK_A 1024   // NROWS / 128

// ---------------- scratch (device globals) ----------------
__device__ __half d_z[NROWS * HID];
__device__ float d_hfc[NROWS * HH];     // h @ Wfc partial logits (4 MB)
__device__ float d_mask[NROWS];
__device__ float d_colpart[NBLK_A * 256];
__device__ float d_ss[256];
__device__ float d_t[NROWS * HH];
__device__ float d_cmax[1024 * HH];
__device__ float d_csum[1024 * HH];
__device__ float d_M[BB * HH];
__device__ float d_invS[BB * HH];
__device__ float d_partial[BB * 64 * HH * FF];
__device__ __half d_WinT[HID * FF];
__device__ __half d_WblkT[HID * HID];

// ---------------- smem layout for kA (bytes) ----------------
#define TILE_BYTES 34816           // 128 * 272
#define AS    0
#define BS0   34816
#define BS1   69632
#define BS2   104448
#define ROWSQ 139264               // 128 floats
#define WSUM  139776               // 8*128 floats
#define WSQ   143872               // 8*128 floats
#define KAWF  147968               // 8 x 136 fp16 WfcT (2176 B)
#define SMEM_TOTAL 150144          // 1 CTA/SM

// ---------------- smem layout for kC (bytes) ----------------
#define KC_WF   34816              // 8 x 136 fp16
#define KC_SC   36992
#define KC_SH   37504
#define KC_BFC  38016
#define KC_STM  38048
#define KC_STS  38304
#define KC_MB   38560
#define KC_SMEM 38592

// ---------------- helpers ----------------
__device__ __forceinline__ uint32_t smem_u32(const void* p) {
    uint32_t a;
    asm("{ .reg .u64 t; cvta.to.shared.u64 t, %1; cvt.u32.u64 %0, t; }" : "=r"(a) : "l"(p));
    return a;
}
__device__ __forceinline__ void ldsm4(uint32_t* r, uint32_t addr) {
    asm volatile("ldmatrix.sync.aligned.m8n8.x4.shared.b16 {%0,%1,%2,%3}, [%4];"
        : "=r"(r[0]), "=r"(r[1]), "=r"(r[2]), "=r"(r[3]) : "r"(addr));
}
__device__ __forceinline__ void ldsm2(uint32_t& r0, uint32_t& r1, uint32_t addr) {
    asm volatile("ldmatrix.sync.aligned.m8n8.x2.shared.b16 {%0,%1}, [%2];"
        : "=r"(r0), "=r"(r1) : "r"(addr));
}
__device__ __forceinline__ void mma16816(float* c, const uint32_t* a, uint32_t b0, uint32_t b1) {
    asm volatile("mma.sync.aligned.m16n8k16.row.col.f32.f16.f16.f32 "
        "{%0,%1,%2,%3}, {%4,%5,%6,%7}, {%8,%9}, {%0,%1,%2,%3};"
        : "+f"(c[0]), "+f"(c[1]), "+f"(c[2]), "+f"(c[3])
        : "r"(a[0]), "r"(a[1]), "r"(a[2]), "r"(a[3]), "r"(b0), "r"(b1));
}
__device__ __forceinline__ uint32_t packh(float a, float b) {
    __half2 hp = __floats2half2_rn(a, b);
    return *reinterpret_cast<uint32_t*>(&hp);
}

// ============================================================================
// kW: convert weights to fp16, transposed to [N][K]
// ============================================================================
__global__ void kW(const float* __restrict__ Win, const float* __restrict__ Wblk) {
    int e = blockIdx.x * 256 + threadIdx.x;
    if (e < HID * FF) {
        int n = e >> 8, k = e & 255;
        d_WinT[e] = __float2half_rn(Win[(size_t)k * HID + n]);
    }
    if (e < HID * HID) {
        int n = e >> 7, k = e & 127;
        d_WblkT[e] = __float2half_rn(Wblk[(size_t)k * HID + n]);
    }
}

// ============================================================================
// kA_mma: h = relu(x@Win+b); z = h@Wblk+b; hfc = h@Wfc; BN partials; mask
// d_h is GONE: the only consumer of h downstream was h@Wfc, computed here
// as a third mini-GEMM (N=8) while the h tile is smem-resident.
// ============================================================================
__global__ __launch_bounds__(512, 1) void kA_mma(
    const float* __restrict__ x, const float* __restrict__ bin,
    const float* __restrict__ bblk, const float* __restrict__ Wfc)
{
    extern __shared__ char smem[];
    const uint32_t sb = smem_u32(smem);
    const int tid = threadIdx.x;
    const int lane = tid & 31;
    const int w = tid >> 5;
    const int wr = w >> 1;
    const int wc = w & 1;
    const int row0 = blockIdx.x * 128;

    float* rowsq = (float*)(smem + ROWSQ);
    float* wS = (float*)(smem + WSUM);
    float* wQ = (float*)(smem + WSQ);
    if (tid < 128) rowsq[tid] = 0.f;

    // persistent B preload: WinT k0, WinT k1, WblkT + WfcT (all L2-hot)
#pragma unroll
    for (int i = 0; i < 4; i++) {
        int idx = tid + i * 512;
        int n = idx >> 4, q = idx & 15;
        uint32_t doff = (uint32_t)(n * 272 + q * 16);
        *(uint4*)(smem + BS0 + doff) = *(const uint4*)(d_WinT + (size_t)n * FF + q * 8);
        *(uint4*)(smem + BS1 + doff) = *(const uint4*)(d_WinT + (size_t)n * FF + 128 + q * 8);
        *(uint4*)(smem + BS2 + doff) = *(const uint4*)(d_WblkT + (size_t)n * HID + q * 8);
    }
#pragma unroll
    for (int u = 0; u < 2; u++) {
        int e = tid + u * 512;    // 0..1023, Wfc[k][j] row-major
        int k = e >> 3, j = e & 7;
        *(__half*)(smem + KAWF + (j * 136 + k) * 2) = __float2half_rn(Wfc[e]);
    }

    float acc[8][4];
#pragma unroll
    for (int nt = 0; nt < 8; nt++)
#pragma unroll
        for (int j = 0; j < 4; j++) acc[nt][j] = 0.f;

    const uint32_t aBase = sb + AS +
        (uint32_t)((wr * 16 + (lane & 15)) * 272 + ((lane >> 4) << 3) * 2);
    const uint32_t laneB = (uint32_t)(wc * 64 * 272 +
        ((lane & 7) + ((lane >> 4) << 3)) * 272 + ((lane >> 3) & 1) * 16);

    // x chunk 0 -> fp16 A + row-nonzero vote
#pragma unroll
    for (int i = 0; i < 8; i++) {
        int idx = tid + i * 512;
        int r = idx >> 5, c4 = idx & 31;
        float4 v = *(const float4*)(x + (size_t)(row0 + r) * FF + c4 * 4);
        int nz = (v.x != 0.f) | (v.y != 0.f) | (v.z != 0.f) | (v.w != 0.f);
        if (__any_sync(0xffffffffu, nz) && lane == 0) rowsq[r] = 1.f;
        *(uint2*)(smem + AS + (uint32_t)(r * 272 + c4 * 8)) =
            make_uint2(packh(v.x, v.y), packh(v.z, v.w));
    }
    __syncthreads();

    // PREFETCH x chunk-1 into registers (completes under MMA chunk 0)
    float4 px[8];
#pragma unroll
    for (int i = 0; i < 8; i++) {
        int idx = tid + i * 512;
        int r = idx >> 5, c4 = idx & 31;
        px[i] = *(const float4*)(x + (size_t)(row0 + r) * FF + 128 + c4 * 4);
    }

    // MMA chunk 0 (B = BS0)
#pragma unroll
    for (int ks = 0; ks < 8; ks++) {
        uint32_t ah[4];
        ldsm4(ah, aBase + ks * 32);
#pragma unroll
        for (int p = 0; p < 4; p++) {
            uint32_t bh[4];
            ldsm4(bh, sb + BS0 + laneB + p * 4352 + ks * 32);
            mma16816(acc[2 * p],     ah, bh[0], bh[1]);
            mma16816(acc[2 * p + 1], ah, bh[2], bh[3]);
        }
    }
    __syncthreads();   // drain chunk-0 A reads

    // x chunk 1: vote + pack from prefetched registers
#pragma unroll
    for (int i = 0; i < 8; i++) {
        int idx = tid + i * 512;
        int r = idx >> 5, c4 = idx & 31;
        float4 v = px[i];
        int nz = (v.x != 0.f) | (v.y != 0.f) | (v.z != 0.f) | (v.w != 0.f);
        if (__any_sync(0xffffffffu, nz) && lane == 0) rowsq[r] = 1.f;
        *(uint2*)(smem + AS + (uint32_t)(r * 272 + c4 * 8)) =
            make_uint2(packh(v.x, v.y), packh(v.z, v.w));
    }
    __syncthreads();

    // MMA chunk 1 (B = BS1)
#pragma unroll
    for (int ks = 0; ks < 8; ks++) {
        uint32_t ah[4];
        ldsm4(ah, aBase + ks * 32);
#pragma unroll
        for (int p = 0; p < 4; p++) {
            uint32_t bh[4];
            ldsm4(bh, sb + BS1 + laneB + p * 4352 + ks * 32);
            mma16816(acc[2 * p],     ah, bh[0], bh[1]);
            mma16816(acc[2 * p + 1], ah, bh[2], bh[3]);
        }
    }
    // RACE FIX: drain GEMM1 A reads before overwriting rows with h
    __syncthreads();

    // epilogue 1: h = relu(acc + bin) -> A smem (fp16 only; no gmem store)
    const int qrow = lane >> 2, qcol = lane & 3;
    const int r0 = wr * 16 + qrow;
#pragma unroll
    for (int nt = 0; nt < 8; nt++) {
        int c0 = wc * 64 + nt * 8 + qcol * 2;
        float b0v = bin[c0], b1v = bin[c0 + 1];
        float h00 = fmaxf(acc[nt][0] + b0v, 0.f);
        float h01 = fmaxf(acc[nt][1] + b1v, 0.f);
        float h10 = fmaxf(acc[nt][2] + b0v, 0.f);
        float h11 = fmaxf(acc[nt][3] + b1v, 0.f);
        *(uint32_t*)(smem + AS + (r0 * 136 + c0) * 2)       = packh(h00, h01);
        *(uint32_t*)(smem + AS + ((r0 + 8) * 136 + c0) * 2) = packh(h10, h11);
        acc[nt][0] = acc[nt][1] = acc[nt][2] = acc[nt][3] = 0.f;
    }
    __syncthreads();

    // GEMM2: z = h @ Wblk (B = BS2)
#pragma unroll
    for (int ks = 0; ks < 8; ks++) {
        uint32_t ah[4];
        ldsm4(ah, aBase + ks * 32);
#pragma unroll
        for (int p = 0; p < 4; p++) {
            uint32_t bh[4];
            ldsm4(bh, sb + BS2 + laneB + p * 4352 + ks * 32);
            mma16816(acc[2 * p],     ah, bh[0], bh[1]);
            mma16816(acc[2 * p + 1], ah, bh[2], bh[3]);
        }
    }

    // GEMM3: hfc = h @ Wfc (N=8) — wc==0 warps only; h tile still resident
    float afc[4] = {0.f, 0.f, 0.f, 0.f};
    if (wc == 0) {
        const uint32_t bFC = sb + KAWF +
            (uint32_t)(((lane & 7) * 136 + ((lane >> 3) & 1) * 8) * 2);
#pragma unroll
        for (int ks = 0; ks < 8; ks++) {
            uint32_t ah[4];
            ldsm4(ah, aBase + ks * 32);
            uint32_t bf0, bf1;
            ldsm2(bf0, bf1, bFC + ks * 32);
            mma16816(afc, ah, bf0, bf1);
        }
        *(float2*)(d_hfc + (size_t)(row0 + r0) * 8 + qcol * 2) =
            make_float2(afc[0], afc[1]);
        *(float2*)(d_hfc + (size_t)(row0 + r0 + 8) * 8 + qcol * 2) =
            make_float2(afc[2], afc[3]);
    }

    // epilogue 2: z + bias, BN partial sums
#pragma unroll
    for (int nt = 0; nt < 8; nt++) {
        int c0 = wc * 64 + nt * 8 + qcol * 2;
        float b0v = bblk[c0], b1v = bblk[c0 + 1];
        float z00 = acc[nt][0] + b0v, z01 = acc[nt][1] + b1v;
        float z10 = acc[nt][2] + b0v, z11 = acc[nt][3] + b1v;
        *(uint32_t*)(d_z + (size_t)(row0 + r0) * HID + c0)     = packh(z00, z01);
        *(uint32_t*)(d_z + (size_t)(row0 + r0 + 8) * HID + c0) = packh(z10, z11);
        float s0 = z00 + z10, s1 = z01 + z11;
        float q0 = z00 * z00 + z10 * z10, q1 = z01 * z01 + z11 * z11;
#pragma unroll
        for (int off = 4; off <= 16; off <<= 1) {
            s0 += __shfl_xor_sync(0xffffffffu, s0, off);
            s1 += __shfl_xor_sync(0xffffffffu, s1, off);
            q0 += __shfl_xor_sync(0xffffffffu, q0, off);
            q1 += __shfl_xor_sync(0xffffffffu, q1, off);
        }
        if (lane < 4) {
            wS[wr * 128 + c0] = s0; wS[wr * 128 + c0 + 1] = s1;
            wQ[wr * 128 + c0] = q0; wQ[wr * 128 + c0 + 1] = q1;
        }
    }
    __syncthreads();
    if (tid < 128) {
        float s = 0.f, q = 0.f;
#pragma unroll
        for (int g = 0; g < 8; g++) { s += wS[g * 128 + tid]; q += wQ[g * 128 + tid]; }
        d_colpart[blockIdx.x * 256 + tid] = s;
        d_colpart[blockIdx.x * 256 + 128 + tid] = q;
        d_mask[row0 + tid] = rowsq[tid];
    }
}

// ============================================================================
// kB: finalize BN stats -> scale/shift
// ============================================================================
__global__ void kB(const float* __restrict__ gamma, const float* __restrict__ beta) {
    __shared__ float rs[256], rq[256];
    int c = blockIdx.x;
    int tid = threadIdx.x;
    float s = 0.f, q = 0.f;
    for (int i = tid; i < NBLK_A; i += 256) {
        s += d_colpart[i * 256 + c];
        q += d_colpart[i * 256 + 128 + c];
    }
    rs[tid] = s; rq[tid] = q;
    __syncthreads();
    for (int st = 128; st > 0; st >>= 1) {
        if (tid < st) { rs[tid] += rs[tid + st]; rq[tid] += rq[tid + st]; }
        __syncthreads();
    }
    if (tid == 0) {
        float mu  = rs[0] * (1.f / (float)NROWS);
        float var = rq[0] * (1.f / (float)NROWS) - mu * mu;
        float sc  = gamma[c] * rsqrtf(var + 1e-5f);
        d_ss[c]       = sc;
        d_ss[128 + c] = beta[c] - mu * sc;
    }
}

// ============================================================================
// kC_mma: t = (relu(bn(z))@Wfc + hfc + bfc)*mask + gumbel  + block stats
// reads only d_z (fp16) + d_hfc — d_h is gone.
// ============================================================================
__global__ __launch_bounds__(256, 2) void kC_mma(
    const float* __restrict__ gumbel, const float* __restrict__ Wfc,
    const float* __restrict__ bfc)
{
    extern __shared__ char smem[];
    const uint32_t sb = smem_u32(smem);
    const int tid = threadIdx.x;
    const int lane = tid & 31;
    const int w = tid >> 5;
    const int row0 = blockIdx.x * 128;

    float* scs  = (float*)(smem + KC_SC);
    float* shs  = (float*)(smem + KC_SH);
    float* bfcs = (float*)(smem + KC_BFC);
    float* stm  = (float*)(smem + KC_STM);
    float* sts  = (float*)(smem + KC_STS);
    float* Mb   = (float*)(smem + KC_MB);

#pragma unroll
    for (int u = 0; u < 4; u++) {
        int e = tid + u * 256;
        int k = e >> 3, j = e & 7;
        *(__half*)(smem + KC_WF + (j * 136 + k) * 2) = __float2half_rn(Wfc[e]);
    }
    if (tid < 128) { scs[tid] = d_ss[tid]; shs[tid] = d_ss[128 + tid]; }
    if (tid < 8)   bfcs[tid] = bfc[tid];
    __syncthreads();

    // convert: relu(bn(z)) tiles per warp (16 x 128), fp16
    char* ah = smem + w * 4352;
    {
        const int c = lane * 4;
        float4 sc4 = *(float4*)(scs + c);
        float4 sh4 = *(float4*)(shs + c);
#pragma unroll
        for (int i = 0; i < 16; i++) {
            size_t g = (size_t)(row0 + w * 16 + i) * HID + c;
            uint2 zp = *(const uint2*)(d_z + g);
            float2 z0 = __half22float2(*(__half2*)&zp.x);
            float2 z1 = __half22float2(*(__half2*)&zp.y);
            float t0 = fmaxf(z0.x * sc4.x + sh4.x, 0.f);
            float t1 = fmaxf(z0.y * sc4.y + sh4.y, 0.f);
            float t2 = fmaxf(z1.x * sc4.z + sh4.z, 0.f);
            float t3 = fmaxf(z1.y * sc4.w + sh4.w, 0.f);
            *(uint2*)(ah + (i * 136 + c) * 2) =
                make_uint2(packh(t0, t1), packh(t2, t3));
        }
    }
    __syncwarp();

    float acc[4] = {0.f, 0.f, 0.f, 0.f};
    const uint32_t aB = sb + w * 4352 +
        (uint32_t)(((lane & 15) * 136 + ((lane >> 4) << 3)) * 2);
    const uint32_t bB = sb + KC_WF +
        (uint32_t)(((lane & 7) * 136 + ((lane >> 3) & 1) * 8) * 2);
#pragma unroll
    for (int ks = 0; ks < 8; ks++) {
        uint32_t ahf[4];
        ldsm4(ahf, aB + ks * 32);
        uint32_t bh0, bh1;
        ldsm2(bh0, bh1, bB + ks * 32);
        mma16816(acc, ahf, bh0, bh1);
    }

    const int qrow = lane >> 2, qcol = lane & 3;
    const int r0 = row0 + w * 16 + qrow;
    float m0v = d_mask[r0], m1v = d_mask[r0 + 8];
    float b0 = bfcs[qcol * 2], b1 = bfcs[qcol * 2 + 1];
    float2 f0 = *(const float2*)(d_hfc + (size_t)r0 * 8 + qcol * 2);
    float2 f1 = *(const float2*)(d_hfc + (size_t)(r0 + 8) * 8 + qcol * 2);
    float2 g0 = *(const float2*)(gumbel + (size_t)r0 * 8 + qcol * 2);
    float2 g1 = *(const float2*)(gumbel + (size_t)(r0 + 8) * 8 + qcol * 2);
    float t00 = (acc[0] + f0.x + b0) * m0v + g0.x;
    float t01 = (acc[1] + f0.y + b1) * m0v + g0.y;
    float t10 = (acc[2] + f1.x + b0) * m1v + g1.x;
    float t11 = (acc[3] + f1.y + b1) * m1v + g1.y;
    *(float2*)(d_t + (size_t)r0 * 8 + qcol * 2)       = make_float2(t00, t01);
    *(float2*)(d_t + (size_t)(r0 + 8) * 8 + qcol * 2) = make_float2(t10, t11);

    // fused softmax stats over this block's 128 rows
    float mx0 = fmaxf(t00, t10), mx1 = fmaxf(t01, t11);
#pragma unroll
    for (int off = 4; off <= 16; off <<= 1) {
        mx0 = fmaxf(mx0, __shfl_xor_sync(0xffffffffu, mx0, off));
        mx1 = fmaxf(mx1, __shfl_xor_sync(0xffffffffu, mx1, off));
    }
    if (lane < 4) { stm[w * 8 + qcol * 2] = mx0; stm[w * 8 + qcol * 2 + 1] = mx1; }
    __syncthreads();
    if (tid < 8) {
        float M = stm[tid];
#pragma unroll
        for (int ww = 1; ww < 8; ww++) M = fmaxf(M, stm[ww * 8 + tid]);
        Mb[tid] = M;
    }
    __syncthreads();
    float M0 = Mb[qcol * 2], M1 = Mb[qcol * 2 + 1];
    float se0 = expf(t00 - M0) + expf(t10 - M0);
    float se1 = expf(t01 - M1) + expf(t11 - M1);
#pragma unroll
    for (int off = 4; off <= 16; off <<= 1) {
        se0 += __shfl_xor_sync(0xffffffffu, se0, off);
        se1 += __shfl_xor_sync(0xffffffffu, se1, off);
    }
    if (lane < 4) { sts[w * 8 + qcol * 2] = se0; sts[w * 8 + qcol * 2 + 1] = se1; }
    __syncthreads();
    if (tid < 8) {
        float S = 0.f;
#pragma unroll
        for (int ww = 0; ww < 8; ww++) S += sts[ww * 8 + tid];
        d_cmax[blockIdx.x * HH + tid] = Mb[tid];
        d_csum[blockIdx.x * HH + tid] = S;
    }
}

// ============================================================================
// kD2: combine 32 chunk stats per b -> global M, invS per (b,h)
// ============================================================================
__global__ void kD2() {
    int b = blockIdx.x, h = threadIdx.x;
    if (h >= 8) return;
    float M = -1e30f;
#pragma unroll
    for (int ch = 0; ch < 32; ch++)
        M = fmaxf(M, d_cmax[(b * 32 + ch) * HH + h]);
    float S = 0.f;
#pragma unroll
    for (int ch = 0; ch < 32; ch++)
        S += d_csum[(b * 32 + ch) * HH + h] * expf(d_cmax[(b * 32 + ch) * HH + h] - M);
    d_M[b * HH + h] = M;
    d_invS[b * HH + h] = 1.f / S;
}

// ============================================================================
// kE: pooled partials with fused softmax normalization
// ============================================================================
__global__ __launch_bounds__(256) void kE(const float* __restrict__ x) {
    __shared__ float wsm[64 * 8];
    __shared__ float Ms[8], iSs[8];
    int b = blockIdx.x >> 4, oc = blockIdx.x & 15;
    int tid = threadIdx.x;
    int fq = tid & 63;
    int og = tid >> 6;
    if (tid < 8)  Ms[tid] = d_M[b * HH + tid];
    if (tid >= 8 && tid < 16) iSs[tid - 8] = d_invS[b * HH + tid - 8];
    float acc[8][4];
#pragma unroll
    for (int h = 0; h < 8; h++)
#pragma unroll
        for (int j = 0; j < 4; j++) acc[h][j] = 0.f;
    int o0 = oc * 256;
    __syncthreads();

    for (int chunk = 0; chunk < 256; chunk += 64) {
        size_t wbase = ((size_t)b * OO + o0 + chunk) * 8;
        {
            int h0 = (tid * 2) & 7;
            float2 tv = *(const float2*)(d_t + wbase + tid * 2);
            wsm[tid * 2]     = expf(tv.x - Ms[h0])     * iSs[h0];
            wsm[tid * 2 + 1] = expf(tv.y - Ms[h0 + 1]) * iSs[h0 + 1];
        }
        __syncthreads();
#pragma unroll 4
        for (int t = 0; t < 16; t++) {
            int oo = og * 16 + t;
            float4 xv = *(const float4*)(x + ((size_t)b * OO + o0 + chunk + oo) * FF + fq * 4);
#pragma unroll
            for (int h = 0; h < 8; h++) {
                float wv = wsm[oo * 8 + h];
                acc[h][0] += wv * xv.x; acc[h][1] += wv * xv.y;
                acc[h][2] += wv * xv.z; acc[h][3] += wv * xv.w;
            }
        }
        __syncthreads();
    }
#pragma unroll
    for (int h = 0; h < 8; h++)
        *(float4*)(d_partial + (((size_t)b * 64 + oc * 4 + og) * 8 + h) * FF + fq * 4) =
            make_float4(acc[h][0], acc[h][1], acc[h][2], acc[h][3]);
}

// ============================================================================
// kF: final reduce over 64 partials
// ============================================================================
__global__ __launch_bounds__(256) void kF(float* __restrict__ out) {
    int bh = blockIdx.x;
    int b = bh >> 3, h = bh & 7;
    int f = threadIdx.x;
    float s = 0.f;
#pragma unroll
    for (int p = 0; p < 64; p++)
        s += d_partial[(((size_t)b * 64 + p) * 8 + h) * FF + f];
    out[(size_t)bh * FF + f] = s;
}

// ============================================================================
extern "C" void kernel_launch(void* const* d_in, const int* in_sizes, int n_in,
                              void* d_out, int out_size) {
    const float* x      = (const float*)d_in[0];
    const float* gumbel = (const float*)d_in[1];
    const float* Win    = (const float*)d_in[2];
    const float* bin    = (const float*)d_in[3];
    const float* Wblk   = (const float*)d_in[4];
    const float* bblk   = (const float*)d_in[5];
    const float* gamma  = (const float*)d_in[6];
    const float* beta   = (const float*)d_in[7];
    const float* Wfc    = (const float*)d_in[8];
    const float* bfc    = (const float*)d_in[9];
    float* out = (float*)d_out;

    cudaFuncSetAttribute(kA_mma, cudaFuncAttributeMaxDynamicSharedMemorySize, SMEM_TOTAL);
    cudaFuncSetAttribute(kC_mma, cudaFuncAttributeMaxDynamicSharedMemorySize, KC_SMEM);

    kW<<<128, 256>>>(Win, Wblk);
    kA_mma<<<NBLK_A, 512, SMEM_TOTAL>>>(x, bin, bblk, Wfc);
    kB<<<128, 256>>>(gamma, beta);
    kC_mma<<<NROWS / 128, 256, KC_SMEM>>>(gumbel, Wfc, bfc);
    kD2<<<BB, 8>>>();
    kE<<<BB * 16, 256>>>(x);
    kF<<<BB * HH, 256>>>(out);
}